// round 7
// baseline (speedup 1.0000x reference)
#include <cuda_runtime.h>
#include <cuda_bf16.h>
#include <math.h>
#include <stdint.h>

// Problem dims (fixed by the dataset)
#define B_   256
#define T_   256
#define D_   128
#define H_   512
#define G3H  1536
#define BT   (B_ * T_)

// ---------------------------------------------------------------------------
// Scratch (static device allocations; harness forbids cudaMalloc)
// ---------------------------------------------------------------------------
__device__ float g_xg[(size_t)BT * G3H];       // 402 MB: xg0 only
__device__ float g_hT[B_ * H_];                // final hidden of layer 1
__device__ uint4 g_wfrag1[32 * 6144];          // Wih1 fragments per jt (3MB, L2-resident)
// h fragments, A-layout, bf16 hi/lo, double buffered
__device__ uint4 g_h0frag[2][2][16 * 32 * 32];
__device__ uint4 g_h1frag[2][2][16 * 32 * 32];

// per-mt-group barrier slots, 128B padded
struct BarSlot { unsigned cnt; volatile unsigned gen; unsigned pad[30]; };
__device__ BarSlot g_bar[4];

// ---------------------------------------------------------------------------
// Group barrier: 32 blocks sharing one mt group. Tight spin.
// ---------------------------------------------------------------------------
__device__ __forceinline__ void group_barrier(int grp) {
    __syncthreads();
    if (threadIdx.x == 0) {
        __threadfence();
        unsigned gen = g_bar[grp].gen;      // read BEFORE arriving
        if (atomicAdd(&g_bar[grp].cnt, 1u) == 31u) {
            atomicExch(&g_bar[grp].cnt, 0u);
            __threadfence();
            g_bar[grp].gen = gen + 1u;
        } else {
            while (g_bar[grp].gen == gen) { }
        }
        __threadfence();
    }
    __syncthreads();
}

// ---------------------------------------------------------------------------
// math helpers
// ---------------------------------------------------------------------------
__device__ __forceinline__ uint32_t f2tf(float f) {
    uint32_t u;
    asm("cvt.rna.tf32.f32 %0, %1;" : "=r"(u) : "f"(f));
    return u;
}

__device__ __forceinline__ void mma_tf32(float* c, const uint32_t* a, const uint32_t* b) {
    asm volatile(
        "mma.sync.aligned.m16n8k8.row.col.f32.tf32.tf32.f32 "
        "{%0,%1,%2,%3}, {%4,%5,%6,%7}, {%8,%9}, {%0,%1,%2,%3};\n"
        : "+f"(c[0]), "+f"(c[1]), "+f"(c[2]), "+f"(c[3])
        : "r"(a[0]), "r"(a[1]), "r"(a[2]), "r"(a[3]), "r"(b[0]), "r"(b[1]));
}

__device__ __forceinline__ void mma_bf16(float* c, const uint4& a, uint32_t b0, uint32_t b1) {
    asm volatile(
        "mma.sync.aligned.m16n8k16.row.col.f32.bf16.bf16.f32 "
        "{%0,%1,%2,%3}, {%4,%5,%6,%7}, {%8,%9}, {%0,%1,%2,%3};\n"
        : "+f"(c[0]), "+f"(c[1]), "+f"(c[2]), "+f"(c[3])
        : "r"(a.x), "r"(a.y), "r"(a.z), "r"(a.w), "r"(b0), "r"(b1));
}

__device__ __forceinline__ uint32_t pack2_bf16(float e0, float e1) {
    __nv_bfloat162 t = __floats2bfloat162_rn(e0, e1);  // .x = low half
    return *(uint32_t*)&t;
}

__device__ __forceinline__ float sigf(float x) {
    return 1.0f / (1.0f + __expf(-x));
}

// Build bf16 hi/lo B-fragments for a 48-col (3 gates x 16) x 512-k weight tile.
__device__ __forceinline__ void build_wfrag(
    uint32_t* Wu, const float* __restrict__ Wsrc, int j0, int tid, int slot_off, int nthreads)
{
    for (int idx = tid; idx < 48 * 256; idx += nthreads) {
        int n  = idx >> 8;
        int k  = (idx & 255) << 1;
        int gate = n >> 4, jj = n & 15;
        const float* wrow = Wsrc + ((size_t)(gate * H_ + j0 + jj)) * H_;
        float w0 = wrow[k], w1 = wrow[k + 1];
        float h0 = __bfloat162float(__float2bfloat16(w0));
        float h1 = __bfloat162float(__float2bfloat16(w1));
        uint32_t hi = pack2_bf16(h0, h1);
        uint32_t lo = pack2_bf16(w0 - h0, w1 - h1);
        int nt = (n >> 3) + slot_off;
        int ks = k >> 4, kr = k & 15;
        int rr   = (kr >= 8) ? 1 : 0;
        int lw   = (n & 7) * 4 + ((kr >> 1) & 3);
        int base = (((nt * 32 + ks) * 32 + lw) << 2);
        Wu[base + rr]     = hi;
        Wu[base + 2 + rr] = lo;
    }
}

// Setup kernel: Wih1 fragments to global (fragment layout, 6 slots per jt)
__global__ void __launch_bounds__(512) build_wih1_kernel(const float* __restrict__ Wih1) {
    int jt = blockIdx.x;
    build_wfrag((uint32_t*)(g_wfrag1 + (size_t)jt * 6144), Wih1, jt * 16, threadIdx.x, 0, 512);
}

// ---------------------------------------------------------------------------
// tf32 tensor-core GEMM for phase 1: xg0 = x @ Wih0^T + bih0
// ---------------------------------------------------------------------------
__global__ void __launch_bounds__(256) gemm_tf32_kernel(
    const float* __restrict__ A, const float* __restrict__ W,
    const float* __restrict__ bias, int K, float* __restrict__ C)
{
    __shared__ uint32_t As[128][36];
    __shared__ uint32_t Bs[128][36];

    const int tid  = threadIdx.x;
    const int m0   = blockIdx.y * 128;
    const int n0   = blockIdx.x * 128;
    const int warp = tid >> 5, lane = tid & 31;
    const int wm = warp >> 2, wn = warp & 3;
    const int g  = lane >> 2, tg = lane & 3;

    float acc[4][4][4] = {};

    for (int k0 = 0; k0 < K; k0 += 32) {
#pragma unroll
        for (int r = 0; r < 4; r++) {
            int f   = tid + (r << 8);
            int row = f >> 3;
            int c4  = (f & 7) << 2;
            float4 va = *(const float4*)(A + (size_t)(m0 + row) * K + k0 + c4);
            As[row][c4 + 0] = f2tf(va.x);
            As[row][c4 + 1] = f2tf(va.y);
            As[row][c4 + 2] = f2tf(va.z);
            As[row][c4 + 3] = f2tf(va.w);
            float4 vb = *(const float4*)(W + (size_t)(n0 + row) * K + k0 + c4);
            Bs[row][c4 + 0] = f2tf(vb.x);
            Bs[row][c4 + 1] = f2tf(vb.y);
            Bs[row][c4 + 2] = f2tf(vb.z);
            Bs[row][c4 + 3] = f2tf(vb.w);
        }
        __syncthreads();

#pragma unroll
        for (int s = 0; s < 4; s++) {
            const int kb = s << 3;
            uint32_t a[4][4], b[4][2];
#pragma unroll
            for (int i = 0; i < 4; i++) {
                int r0 = wm * 64 + i * 16 + g;
                a[i][0] = As[r0][kb + tg];
                a[i][1] = As[r0 + 8][kb + tg];
                a[i][2] = As[r0][kb + tg + 4];
                a[i][3] = As[r0 + 8][kb + tg + 4];
            }
#pragma unroll
            for (int jx = 0; jx < 4; jx++) {
                int c = wn * 32 + jx * 8 + g;
                b[jx][0] = Bs[c][kb + tg];
                b[jx][1] = Bs[c][kb + tg + 4];
            }
#pragma unroll
            for (int i = 0; i < 4; i++)
#pragma unroll
                for (int jx = 0; jx < 4; jx++)
                    mma_tf32(acc[i][jx], a[i], b[jx]);
        }
        __syncthreads();
    }

#pragma unroll
    for (int i = 0; i < 4; i++) {
        int r0 = m0 + wm * 64 + i * 16 + g;
#pragma unroll
        for (int jx = 0; jx < 4; jx++) {
            int col = n0 + wn * 32 + jx * 8 + tg * 2;
            float2 bv = *(const float2*)(bias + col);
            float2 o0 = make_float2(acc[i][jx][0] + bv.x, acc[i][jx][1] + bv.y);
            float2 o1 = make_float2(acc[i][jx][2] + bv.x, acc[i][jx][3] + bv.y);
            *(float2*)(C + (size_t)r0 * G3H + col)       = o0;
            *(float2*)(C + (size_t)(r0 + 8) * G3H + col) = o1;
        }
    }
}

#define CS0 50
#define CS1 66

// rec1 MMA + stage, templated on WN (warp's n-half). Merged accumulation for
// r/z gate columns; split (xn vs hn) for n-gate columns (WN==1, nt>=1).
template<int WN>
__device__ __forceinline__ void rec1_step(
    float* Csm1, const uint4* __restrict__ Wf, const uint4* __restrict__ Wih,
    const uint4* __restrict__ A0h, const uint4* __restrict__ A0l,
    const uint4* __restrict__ A1h, const uint4* __restrict__ A1l,
    int m16, int lane, int wm)
{
    const int g = lane >> 2, tg = lane & 3;
    float C[3][4] = {};
    float Ci[2][4] = {};
#pragma unroll 2
    for (int ks = 0; ks < 32; ks++) {
        size_t fidx = ((size_t)(m16 * 32 + ks)) * 32 + lane;
        uint4 a0h = A0h[fidx], a0l = A0l[fidx];
        uint4 a1h = A1h[fidx], a1l = A1l[fidx];
#pragma unroll
        for (int nt = 0; nt < 3; nt++) {
            uint4 wh = Wf[((6 + WN * 3 + nt) * 32 + ks) * 32 + lane];
            mma_bf16(C[nt], a1h, wh.x, wh.y);
            mma_bf16(C[nt], a1h, wh.z, wh.w);
            mma_bf16(C[nt], a1l, wh.x, wh.y);
            uint4 wi = Wih[((WN * 3 + nt) * 32 + ks) * 32 + lane];
            if (WN == 1 && nt >= 1) {
                mma_bf16(Ci[nt - 1], a0h, wi.x, wi.y);
                mma_bf16(Ci[nt - 1], a0h, wi.z, wi.w);
                mma_bf16(Ci[nt - 1], a0l, wi.x, wi.y);
            } else {
                mma_bf16(C[nt], a0h, wi.x, wi.y);
                mma_bf16(C[nt], a0h, wi.z, wi.w);
                mma_bf16(C[nt], a0l, wi.x, wi.y);
            }
        }
    }
    const int r0 = wm * 16 + g;
#pragma unroll
    for (int nt = 0; nt < 3; nt++) {
        int cb = (WN * 3 + nt) * 8 + 2 * tg;
        if (WN == 1 && nt >= 1) {
            *(float2*)&Csm1[r0 * CS1 + cb]            = make_float2(Ci[nt - 1][0], Ci[nt - 1][1]);
            *(float2*)&Csm1[(r0 + 8) * CS1 + cb]      = make_float2(Ci[nt - 1][2], Ci[nt - 1][3]);
            *(float2*)&Csm1[r0 * CS1 + cb + 16]       = make_float2(C[nt][0], C[nt][1]);
            *(float2*)&Csm1[(r0 + 8) * CS1 + cb + 16] = make_float2(C[nt][2], C[nt][3]);
        } else {
            *(float2*)&Csm1[r0 * CS1 + cb]       = make_float2(C[nt][0], C[nt][1]);
            *(float2*)&Csm1[(r0 + 8) * CS1 + cb] = make_float2(C[nt][2], C[nt][3]);
        }
    }
}

// ---------------------------------------------------------------------------
// FUSED two-layer GRU: 257 barrier windows. Window t:
//   warps 0-7  : h0(t)   = GRU0(h0(t-1), xg0[t])              [t < 256]
//   warps 8-15 : h1(t-1) = GRU1(h1(t-2), y0(t-1)=h0(t-1))     [t >= 1]
// Whh0 + Whh1 fragments in smem; Wih1 fragments streamed from L2.
// Epilogue: 128 frag-threads per layer, 8 outputs each, packs from registers.
// ---------------------------------------------------------------------------
__global__ void __launch_bounds__(512, 1) gru_fused_kernel(
    const float* __restrict__ Whh0, const float* __restrict__ bhh0,
    const float* __restrict__ Whh1, const float* __restrict__ bhh1,
    const float* __restrict__ bih1)
{
    extern __shared__ char smraw[];
    uint4* Wf   = (uint4*)smraw;                            // 12*32*32 uint4 = 192KB
    float* Csm0 = (float*)(smraw + 12 * 32 * 32 * 16);      // 64 x 50
    float* Csm1 = Csm0 + 64 * CS0;                          // 64 x 66

    const int tid = threadIdx.x;
    const int bid = blockIdx.x;
    const int jt  = bid & 31, mt = bid >> 5;
    const int m0  = mt * 64, j0 = jt * 16;
    const int w   = tid >> 5, lane = tid & 31;
    const int task = w >> 3, wsub = w & 7;
    const int wm  = wsub >> 1, wn = wsub & 1;
    const int g   = lane >> 2, tg = lane & 3;
    const int m16 = mt * 4 + wm;

    build_wfrag((uint32_t*)Wf, Whh0, j0, tid, 0, 512);
    build_wfrag((uint32_t*)Wf, Whh1, j0, tid, 6, 512);

    // zero init: h0frag buffer 0, h1frag buffer 1 (group-local slices)
    {
        int idx = (bid & 31) * 512 + tid;      // 0..16383
        uint4 z = make_uint4(0, 0, 0, 0);
        size_t base = (size_t)mt * 4096;
        if      (idx < 4096)  g_h0frag[0][0][base + idx] = z;
        else if (idx < 8192)  g_h0frag[0][1][base + idx - 4096] = z;
        else if (idx < 12288) g_h1frag[1][0][base + idx - 8192] = z;
        else                  g_h1frag[1][1][base + idx - 12288] = z;
    }

    // epilogue geometry (frag-thread view)
    const bool ep0 = (tid < 128);
    const bool ep1 = (tid >= 128) && (tid < 256);
    const int f    = tid & 127;
    const int m16l = f >> 5, ln = f & 31;
    const int g2   = ln >> 2, tg2 = ln & 3;
    const int er0  = m16l * 16 + g2, er1 = er0 + 8;
    const int k0   = tg2 * 2;

    // biases per epilogue col set {k0, k0+1, k0+8, k0+9}
    float br0[4], bz0[4], bn0[4];
    float Br1[4], Bz1[4], bxn1[4], bhn1[4];
    {
        int cols[4] = {j0 + k0, j0 + k0 + 1, j0 + k0 + 8, j0 + k0 + 9};
#pragma unroll
        for (int c = 0; c < 4; c++) {
            br0[c]  = bhh0[cols[c]];
            bz0[c]  = bhh0[H_ + cols[c]];
            bn0[c]  = bhh0[2 * H_ + cols[c]];
            Br1[c]  = bih1[cols[c]] + bhh1[cols[c]];
            Bz1[c]  = bih1[H_ + cols[c]] + bhh1[H_ + cols[c]];
            bxn1[c] = bih1[2 * H_ + cols[c]];
            bhn1[c] = bhh1[2 * H_ + cols[c]];
        }
    }

    float hreg0[8] = {0,0,0,0,0,0,0,0};
    float hreg1[8] = {0,0,0,0,0,0,0,0};

    const uint4* Wih = g_wfrag1 + (size_t)jt * 6144;

    // xg0 prefetch buffers (ep0 threads)
    float xr[8], xz[8], xn[8];
    auto prefetch_xg = [&](int t) {
#pragma unroll
        for (int pr = 0; pr < 4; pr++) {
            int row = (pr & 1) ? er1 : er0;
            int cp  = (pr & 2) ? (k0 + 8) : k0;
            size_t base = ((size_t)(m0 + row) * T_ + t) * G3H + j0 + cp;
            float2 vr = *(const float2*)(g_xg + base);
            float2 vz = *(const float2*)(g_xg + base + H_);
            float2 vn = *(const float2*)(g_xg + base + 2 * H_);
            xr[2 * pr] = vr.x; xr[2 * pr + 1] = vr.y;
            xz[2 * pr] = vz.x; xz[2 * pr + 1] = vz.y;
            xn[2 * pr] = vn.x; xn[2 * pr + 1] = vn.y;
        }
    };
    if (ep0) prefetch_xg(0);

    group_barrier(mt);

    for (int t = 0; t <= 256; t++) {
        // ================= MMA phase =================
        if (task == 0) {
            if (t < 256) {
                const uint4* __restrict__ Ahi = g_h0frag[t & 1][0];
                const uint4* __restrict__ Alo = g_h0frag[t & 1][1];
                float C[3][4] = {};
#pragma unroll 4
                for (int ks = 0; ks < 32; ks++) {
                    size_t fidx = ((size_t)(m16 * 32 + ks)) * 32 + lane;
                    uint4 ahi = Ahi[fidx];
                    uint4 alo = Alo[fidx];
#pragma unroll
                    for (int nt = 0; nt < 3; nt++) {
                        uint4 wf = Wf[((wn * 3 + nt) * 32 + ks) * 32 + lane];
                        mma_bf16(C[nt], ahi, wf.x, wf.y);
                        mma_bf16(C[nt], ahi, wf.z, wf.w);
                        mma_bf16(C[nt], alo, wf.x, wf.y);
                    }
                }
                const int r0s = wm * 16 + g;
#pragma unroll
                for (int nt = 0; nt < 3; nt++) {
                    int cb = (wn * 3 + nt) * 8 + 2 * tg;
                    *(float2*)&Csm0[r0s * CS0 + cb]       = make_float2(C[nt][0], C[nt][1]);
                    *(float2*)&Csm0[(r0s + 8) * CS0 + cb] = make_float2(C[nt][2], C[nt][3]);
                }
            }
        } else {
            if (t >= 1) {
                const uint4* A0h = g_h0frag[t & 1][0];
                const uint4* A0l = g_h0frag[t & 1][1];
                const uint4* A1h = g_h1frag[t & 1][0];
                const uint4* A1l = g_h1frag[t & 1][1];
                if (wn == 0)
                    rec1_step<0>(Csm1, Wf, Wih, A0h, A0l, A1h, A1l, m16, lane, wm);
                else
                    rec1_step<1>(Csm1, Wf, Wih, A0h, A0l, A1h, A1l, m16, lane, wm);
            }
        }
        __syncthreads();

        // ================= epilogue =================
        if (ep0 && t < 256) {
            float hv[8];
#pragma unroll
            for (int q = 0; q < 8; q++) {
                int mlq = (q & 2) ? er1 : er0;
                int jcq = k0 + (q & 1) + ((q & 4) ? 8 : 0);
                int c   = (q & 1) + ((q & 4) ? 2 : 0);
                float cr = Csm0[mlq * CS0 + jcq];
                float cz = Csm0[mlq * CS0 + 16 + jcq];
                float cn = Csm0[mlq * CS0 + 32 + jcq];
                float r = sigf(xr[q] + cr + br0[c]);
                float z = sigf(xz[q] + cz + bz0[c]);
                float n = tanhf(xn[q] + r * (cn + bn0[c]));
                float h = (1.0f - z) * n + z * hreg0[q];
                hreg0[q] = h;
                hv[q] = h;
            }
            float fh[8], fl[8];
#pragma unroll
            for (int q = 0; q < 8; q++) {
                fh[q] = __bfloat162float(__float2bfloat16(hv[q]));
                fl[q] = hv[q] - fh[q];
            }
            uint4 hi, lo;
            hi.x = pack2_bf16(fh[0], fh[1]); hi.y = pack2_bf16(fh[2], fh[3]);
            hi.z = pack2_bf16(fh[4], fh[5]); hi.w = pack2_bf16(fh[6], fh[7]);
            lo.x = pack2_bf16(fl[0], fl[1]); lo.y = pack2_bf16(fl[2], fl[3]);
            lo.z = pack2_bf16(fl[4], fl[5]); lo.w = pack2_bf16(fl[6], fl[7]);
            size_t fb = ((size_t)((mt * 4 + m16l) * 32 + jt)) * 32 + ln;
            g_h0frag[(t + 1) & 1][0][fb] = hi;
            g_h0frag[(t + 1) & 1][1][fb] = lo;
        }

        if (ep1 && t >= 1) {
            float hv[8];
#pragma unroll
            for (int q = 0; q < 8; q++) {
                int mlq = (q & 2) ? er1 : er0;
                int jcq = k0 + (q & 1) + ((q & 4) ? 8 : 0);
                int c   = (q & 1) + ((q & 4) ? 2 : 0);
                float cr  = Csm1[mlq * CS1 + jcq];
                float cz  = Csm1[mlq * CS1 + 16 + jcq];
                float cxn = Csm1[mlq * CS1 + 32 + jcq];
                float chn = Csm1[mlq * CS1 + 48 + jcq];
                float r = sigf(cr + Br1[c]);
                float z = sigf(cz + Bz1[c]);
                float n = tanhf(cxn + bxn1[c] + r * (chn + bhn1[c]));
                float h = (1.0f - z) * n + z * hreg1[q];
                hreg1[q] = h;
                hv[q] = h;
            }
            if (t == 256) {
#pragma unroll
                for (int q = 0; q < 8; q++) {
                    int mlq = (q & 2) ? er1 : er0;
                    int jcq = k0 + (q & 1) + ((q & 4) ? 8 : 0);
                    g_hT[(size_t)(m0 + mlq) * H_ + j0 + jcq] = hv[q];
                }
            } else {
                float fh[8], fl[8];
#pragma unroll
                for (int q = 0; q < 8; q++) {
                    fh[q] = __bfloat162float(__float2bfloat16(hv[q]));
                    fl[q] = hv[q] - fh[q];
                }
                uint4 hi, lo;
                hi.x = pack2_bf16(fh[0], fh[1]); hi.y = pack2_bf16(fh[2], fh[3]);
                hi.z = pack2_bf16(fh[4], fh[5]); hi.w = pack2_bf16(fh[6], fh[7]);
                lo.x = pack2_bf16(fl[0], fl[1]); lo.y = pack2_bf16(fl[2], fl[3]);
                lo.z = pack2_bf16(fl[4], fl[5]); lo.w = pack2_bf16(fl[6], fl[7]);
                size_t fb = ((size_t)((mt * 4 + m16l) * 32 + jt)) * 32 + ln;
                g_h1frag[(t + 1) & 1][0][fb] = hi;
                g_h1frag[(t + 1) & 1][1][fb] = lo;
            }
        }

        // prefetch xg0 for next window (independent of h state)
        if (ep0 && t < 255) prefetch_xg(t + 1);

        group_barrier(mt);
    }
}

// ---------------------------------------------------------------------------
// Head: out = relu(relu(hT) @ fc1^T + b1) @ fc2^T + b2
// ---------------------------------------------------------------------------
__global__ void __launch_bounds__(512) head_kernel(
    const float* __restrict__ w1, const float* __restrict__ b1,
    const float* __restrict__ w2, const float* __restrict__ b2,
    float* __restrict__ out)
{
    __shared__ float sh[H_];
    __shared__ float s1[128];
    const int b = blockIdx.x;
    const int tid = threadIdx.x;
    const int w = tid >> 5, lane = tid & 31;

    sh[tid] = fmaxf(g_hT[(size_t)b * H_ + tid], 0.0f);
    __syncthreads();

#pragma unroll
    for (int oo = 0; oo < 8; oo++) {
        int o = w * 8 + oo;
        const float* wr = w1 + (size_t)o * H_;
        float acc = 0.f;
#pragma unroll
        for (int c = 0; c < 4; c++) {
            int k = c * 128 + lane * 4;
            float4 wv = *(const float4*)(wr + k);
            float4 hv = *(const float4*)(&sh[k]);
            acc += wv.x * hv.x + wv.y * hv.y + wv.z * hv.z + wv.w * hv.w;
        }
#pragma unroll
        for (int off = 16; off; off >>= 1)
            acc += __shfl_down_sync(0xFFFFFFFFu, acc, off);
        if (lane == 0) s1[o] = fmaxf(acc + b1[o], 0.0f);
    }
    __syncthreads();

    if (w < 10) {
        const float* wr = w2 + (size_t)w * 128;
        float acc = 0.f;
#pragma unroll
        for (int c = 0; c < 4; c++) {
            int k = lane + c * 32;
            acc += s1[k] * wr[k];
        }
#pragma unroll
        for (int off = 16; off; off >>= 1)
            acc += __shfl_down_sync(0xFFFFFFFFu, acc, off);
        if (lane == 0) out[(size_t)b * 10 + w] = acc + b2[w];
    }
}

// ---------------------------------------------------------------------------
// Launch
// ---------------------------------------------------------------------------
extern "C" void kernel_launch(void* const* d_in, const int* in_sizes, int n_in,
                              void* d_out, int out_size)
{
    const float* x    = (const float*)d_in[0];
    const float* Wih0 = (const float*)d_in[1];
    const float* Whh0 = (const float*)d_in[2];
    const float* bih0 = (const float*)d_in[3];
    const float* bhh0 = (const float*)d_in[4];
    const float* Wih1 = (const float*)d_in[5];
    const float* Whh1 = (const float*)d_in[6];
    const float* bih1 = (const float*)d_in[7];
    const float* bhh1 = (const float*)d_in[8];
    const float* fc1w = (const float*)d_in[9];
    const float* fc1b = (const float*)d_in[10];
    const float* fc2w = (const float*)d_in[11];
    const float* fc2b = (const float*)d_in[12];
    float* out = (float*)d_out;

    float* xg_ptr = nullptr;
    cudaGetSymbolAddress((void**)&xg_ptr, g_xg);

    const int fused_smem = 12 * 32 * 32 * 16 + (64 * CS0 + 64 * CS1) * 4;  // 226304
    cudaFuncSetAttribute((const void*)gru_fused_kernel,
                         cudaFuncAttributeMaxDynamicSharedMemorySize, fused_smem);

    dim3 gemm_grid(G3H / 128, BT / 128);  // (12, 512)

    // Phase 0: build Wih1 fragment table (3MB, L2-resident)
    build_wih1_kernel<<<32, 512>>>(Wih1);

    // Phase 1: xg0 = x @ W_ih0^T + b_ih0   (K = 128)
    gemm_tf32_kernel<<<gemm_grid, 256>>>(x, Wih0, bih0, D_, xg_ptr);

    // Phase 2: fused two-layer GRU (257 barrier windows)
    gru_fused_kernel<<<128, 512, fused_smem>>>(Whh0, bhh0, Whh1, bhh1, bih1);

    // Phase 3: MLP head
    head_kernel<<<B_, 512>>>(fc1w, fc1b, fc2w, fc2b, out);
}

// round 8
// speedup vs baseline: 1.4736x; 1.4736x over previous
#include <cuda_runtime.h>
#include <cuda_bf16.h>
#include <math.h>
#include <stdint.h>

// Problem dims (fixed by the dataset)
#define B_   256
#define T_   256
#define D_   128
#define H_   512
#define G3H  1536
#define BT   (B_ * T_)

// ---------------------------------------------------------------------------
// Scratch (static device allocations; harness forbids cudaMalloc)
// ---------------------------------------------------------------------------
__device__ float g_xg[(size_t)BT * G3H];   // 402 MB: xg0, overwritten in-place by xg1
__device__ float g_hT[B_ * H_];            // final hidden of layer 1
// h in A-fragment order, bf16 hi/lo, double buffered
__device__ uint4 g_hfrag[2][2][16 * 32 * 32];

// Slot barrier: [group][block][pad] — each slot on its own 128B line.
// Monotonic gens; each block snapshots ITS OWN slot at kernel start (only the
// block itself ever writes that slot, and every block of a group stores the
// same number of gens per kernel, so snapshots agree) -> replay-safe.
__device__ volatile unsigned g_slot[4][32][32];

__device__ __forceinline__ void slot_barrier(int grp, int blk, unsigned gen) {
    __syncthreads();
    if (threadIdx.x == 0) {
        __threadfence();                    // release own writes
        g_slot[grp][blk][0] = gen;
    }
    if (threadIdx.x < 32) {
        while ((int)(g_slot[grp][threadIdx.x][0] - gen) < 0) { }
        __threadfence();                    // acquire (invalidates stale L1)
    }
    __syncthreads();
}

// ---------------------------------------------------------------------------
// math helpers
// ---------------------------------------------------------------------------
__device__ __forceinline__ uint32_t f2tf(float f) {
    uint32_t u;
    asm("cvt.rna.tf32.f32 %0, %1;" : "=r"(u) : "f"(f));
    return u;
}

__device__ __forceinline__ void mma_tf32(float* c, const uint32_t* a, const uint32_t* b) {
    asm volatile(
        "mma.sync.aligned.m16n8k8.row.col.f32.tf32.tf32.f32 "
        "{%0,%1,%2,%3}, {%4,%5,%6,%7}, {%8,%9}, {%0,%1,%2,%3};\n"
        : "+f"(c[0]), "+f"(c[1]), "+f"(c[2]), "+f"(c[3])
        : "r"(a[0]), "r"(a[1]), "r"(a[2]), "r"(a[3]), "r"(b[0]), "r"(b[1]));
}

__device__ __forceinline__ void mma_bf16(float* c, const uint4& a, uint32_t b0, uint32_t b1) {
    asm volatile(
        "mma.sync.aligned.m16n8k16.row.col.f32.bf16.bf16.f32 "
        "{%0,%1,%2,%3}, {%4,%5,%6,%7}, {%8,%9}, {%0,%1,%2,%3};\n"
        : "+f"(c[0]), "+f"(c[1]), "+f"(c[2]), "+f"(c[3])
        : "r"(a.x), "r"(a.y), "r"(a.z), "r"(a.w), "r"(b0), "r"(b1));
}

__device__ __forceinline__ uint32_t pack2_bf16(float e0, float e1) {
    __nv_bfloat162 t = __floats2bfloat162_rn(e0, e1);  // .x = low half
    return *(uint32_t*)&t;
}

__device__ __forceinline__ float sigf(float x) {
    return 1.0f / (1.0f + __expf(-x));
}

// Build bf16 hi/lo B-fragments for a 48-col (3 gates x 16) x 512-k weight tile.
__device__ __forceinline__ void build_wfrag(
    uint32_t* Wu, const float* __restrict__ Wsrc, int j0, int tid, int slot_off, int nthreads)
{
    for (int idx = tid; idx < 48 * 256; idx += nthreads) {
        int n  = idx >> 8;
        int k  = (idx & 255) << 1;
        int gate = n >> 4, jj = n & 15;
        const float* wrow = Wsrc + ((size_t)(gate * H_ + j0 + jj)) * H_;
        float w0 = wrow[k], w1 = wrow[k + 1];
        float h0 = __bfloat162float(__float2bfloat16(w0));
        float h1 = __bfloat162float(__float2bfloat16(w1));
        uint32_t hi = pack2_bf16(h0, h1);
        uint32_t lo = pack2_bf16(w0 - h0, w1 - h1);
        int nt = (n >> 3) + slot_off;
        int ks = k >> 4, kr = k & 15;
        int rr   = (kr >= 8) ? 1 : 0;
        int lw   = (n & 7) * 4 + ((kr >> 1) & 3);
        int base = (((nt * 32 + ks) * 32 + lw) << 2);
        Wu[base + rr]     = hi;
        Wu[base + 2 + rr] = lo;
    }
}

// ---------------------------------------------------------------------------
// tf32 tensor-core GEMM (phase 1): xg0 = x @ Wih0^T + bih0
// ---------------------------------------------------------------------------
__global__ void __launch_bounds__(256) gemm_tf32_kernel(
    const float* __restrict__ A, const float* __restrict__ W,
    const float* __restrict__ bias, int K, float* __restrict__ C)
{
    __shared__ uint32_t As[128][36];
    __shared__ uint32_t Bs[128][36];

    const int tid  = threadIdx.x;
    const int m0   = blockIdx.y * 128;
    const int n0   = blockIdx.x * 128;
    const int warp = tid >> 5, lane = tid & 31;
    const int wm = warp >> 2, wn = warp & 3;
    const int g  = lane >> 2, tg = lane & 3;

    float acc[4][4][4] = {};

    for (int k0 = 0; k0 < K; k0 += 32) {
#pragma unroll
        for (int r = 0; r < 4; r++) {
            int f   = tid + (r << 8);
            int row = f >> 3;
            int c4  = (f & 7) << 2;
            float4 va = *(const float4*)(A + (size_t)(m0 + row) * K + k0 + c4);
            As[row][c4 + 0] = f2tf(va.x);
            As[row][c4 + 1] = f2tf(va.y);
            As[row][c4 + 2] = f2tf(va.z);
            As[row][c4 + 3] = f2tf(va.w);
            float4 vb = *(const float4*)(W + (size_t)(n0 + row) * K + k0 + c4);
            Bs[row][c4 + 0] = f2tf(vb.x);
            Bs[row][c4 + 1] = f2tf(vb.y);
            Bs[row][c4 + 2] = f2tf(vb.z);
            Bs[row][c4 + 3] = f2tf(vb.w);
        }
        __syncthreads();

#pragma unroll
        for (int s = 0; s < 4; s++) {
            const int kb = s << 3;
            uint32_t a[4][4], b[4][2];
#pragma unroll
            for (int i = 0; i < 4; i++) {
                int r0 = wm * 64 + i * 16 + g;
                a[i][0] = As[r0][kb + tg];
                a[i][1] = As[r0 + 8][kb + tg];
                a[i][2] = As[r0][kb + tg + 4];
                a[i][3] = As[r0 + 8][kb + tg + 4];
            }
#pragma unroll
            for (int jx = 0; jx < 4; jx++) {
                int c = wn * 32 + jx * 8 + g;
                b[jx][0] = Bs[c][kb + tg];
                b[jx][1] = Bs[c][kb + tg + 4];
            }
#pragma unroll
            for (int i = 0; i < 4; i++)
#pragma unroll
                for (int jx = 0; jx < 4; jx++)
                    mma_tf32(acc[i][jx], a[i], b[jx]);
        }
        __syncthreads();
    }

#pragma unroll
    for (int i = 0; i < 4; i++) {
        int r0 = m0 + wm * 64 + i * 16 + g;
#pragma unroll
        for (int jx = 0; jx < 4; jx++) {
            int col = n0 + wn * 32 + jx * 8 + tg * 2;
            float2 bv = *(const float2*)(bias + col);
            float2 o0 = make_float2(acc[i][jx][0] + bv.x, acc[i][jx][1] + bv.y);
            float2 o1 = make_float2(acc[i][jx][2] + bv.x, acc[i][jx][3] + bv.y);
            *(float2*)(C + (size_t)r0 * G3H + col)       = o0;
            *(float2*)(C + (size_t)(r0 + 8) * G3H + col) = o1;
        }
    }
}

#define CSTRIDE 50
#define HSTRIDE 17

// ---------------------------------------------------------------------------
// h-fragment pack (coalesced uint4 stores), 128 threads
// ---------------------------------------------------------------------------
__device__ __forceinline__ void pack_hfrag(
    const float* Hsm, int mt, int jt, int t, int tid)
{
    if (tid < 128) {
        const int m16l = tid >> 5;
        const int ln   = tid & 31;
        const int gg   = ln >> 2, tg2 = ln & 3;
        const int r0 = m16l * 16 + gg, r1 = r0 + 8;
        const int k0 = tg2 * 2;

        float v[8];
        v[0] = Hsm[r0 * HSTRIDE + k0];     v[1] = Hsm[r0 * HSTRIDE + k0 + 1];
        v[2] = Hsm[r1 * HSTRIDE + k0];     v[3] = Hsm[r1 * HSTRIDE + k0 + 1];
        v[4] = Hsm[r0 * HSTRIDE + k0 + 8]; v[5] = Hsm[r0 * HSTRIDE + k0 + 9];
        v[6] = Hsm[r1 * HSTRIDE + k0 + 8]; v[7] = Hsm[r1 * HSTRIDE + k0 + 9];

        float fh[8], fl[8];
#pragma unroll
        for (int q = 0; q < 8; q++) {
            fh[q] = __bfloat162float(__float2bfloat16(v[q]));
            fl[q] = v[q] - fh[q];
        }
        uint4 hi, lo;
        hi.x = pack2_bf16(fh[0], fh[1]); hi.y = pack2_bf16(fh[2], fh[3]);
        hi.z = pack2_bf16(fh[4], fh[5]); hi.w = pack2_bf16(fh[6], fh[7]);
        lo.x = pack2_bf16(fl[0], fl[1]); lo.y = pack2_bf16(fl[2], fl[3]);
        lo.z = pack2_bf16(fl[4], fl[5]); lo.w = pack2_bf16(fl[6], fl[7]);

        const int nb = (t + 1) & 1;
        size_t base = ((size_t)((mt * 4 + m16l) * 32 + jt)) * 32 + ln;
        g_hfrag[nb][0][base] = hi;
        g_hfrag[nb][1][base] = lo;
    }
}

// ---------------------------------------------------------------------------
// FUSED layer-0 recurrence + layer-1 input projection. 512 threads, task-split:
// warps 0-7 do the recurrent GEMM, warps 8-15 do the xg1 GEMM (same A frags).
// ---------------------------------------------------------------------------
__global__ void __launch_bounds__(512, 1) gru_rec0_fused_kernel(
    const float* __restrict__ Whh, const float* __restrict__ bhh,
    const float* __restrict__ Wih1, const float* __restrict__ bih1)
{
    extern __shared__ char smraw[];
    uint4* Wf   = (uint4*)smraw;                               // 12*32*32 uint4 = 192KB
    float* Csm  = (float*)(smraw + 12 * 32 * 32 * 16);         // 64 x CSTRIDE
    float* Hsm  = Csm + 64 * CSTRIDE;                          // 64 x HSTRIDE

    const int tid  = threadIdx.x;
    const int bid  = blockIdx.x;
    const int jt   = bid & 31, mt = bid >> 5;
    const int m0   = mt * 64, j0 = jt * 16;
    const int w    = tid >> 5, lane = tid & 31;
    const int task = w >> 3;                    // 0 = rec, 1 = xg1
    const int wm   = (w >> 1) & 3, wn = w & 1;
    const int g    = lane >> 2, tg = lane & 3;
    const int m16  = mt * 4 + wm;
    const int tx   = tid & 15;
    const int row2 = (tid >> 4) << 1;           // 0..62, 2 rows per thread
    const int j    = j0 + tx;

    // barrier gen snapshot (own slot; only this block writes it)
    unsigned bgen = 0;
    if (tid < 32) bgen = g_slot[mt][jt][0];
    unsigned genc = 0;

    build_wfrag((uint32_t*)Wf, Whh,  j0, tid, 0, 512);
    build_wfrag((uint32_t*)Wf, Wih1, j0, tid, 6, 512);

    // ---- Zero h fragment buffer 0 for THIS group only ----
    {
        int idx = (bid & 31) * 512 + tid;
        size_t base = (size_t)mt * 4096;
        uint4 z = make_uint4(0, 0, 0, 0);
        if (idx < 4096)      g_hfrag[0][0][base + idx] = z;
        else if (idx < 8192) g_hfrag[0][1][base + idx - 4096] = z;
    }

    const float bb0 = bhh[j];
    const float bb1 = bhh[H_ + j];
    const float bb2 = bhh[2 * H_ + j];

    // xg1 epilogue bias pairs (task-1 warps)
    float2 bx[3];
    int    gcolv[3];
#pragma unroll
    for (int nt = 0; nt < 3; nt++) {
        int n0c  = (wn * 3 + nt) * 8 + 2 * tg;
        int gate = n0c >> 4, jj = n0c & 15;
        int gcol = gate * H_ + j0 + jj;
        gcolv[nt] = gcol;
        bx[nt] = make_float2(bih1[gcol], bih1[gcol + 1]);
    }

    float hreg[2] = {0.f, 0.f};

    float xr[2], xz[2], xn[2];
#pragma unroll
    for (int i = 0; i < 2; i++) {
        size_t xb = ((size_t)(m0 + row2 + i) * T_ + 0) * G3H + j;
        xr[i] = g_xg[xb]; xz[i] = g_xg[xb + H_]; xn[i] = g_xg[xb + 2 * H_];
    }

    slot_barrier(mt, jt, bgen + (++genc));

    const size_t fb0 = (size_t)(m16 * 32) * 32 + lane;

    for (int t = 0; t < T_; t++) {
        const uint4* __restrict__ Ahi = g_hfrag[t & 1][0];
        const uint4* __restrict__ Alo = g_hfrag[t & 1][1];

        if (task == 0) {
            float C[3][4] = {};
            uint4 ahi = Ahi[fb0], alo = Alo[fb0];
#pragma unroll 4
            for (int ks = 0; ks < 32; ks++) {
                uint4 nh, nl;
                if (ks < 31) { nh = Ahi[fb0 + (ks + 1) * 32]; nl = Alo[fb0 + (ks + 1) * 32]; }
#pragma unroll
                for (int nt = 0; nt < 3; nt++) {
                    uint4 wf = Wf[((wn * 3 + nt) * 32 + ks) * 32 + lane];
                    mma_bf16(C[nt], ahi, wf.x, wf.y);
                    mma_bf16(C[nt], ahi, wf.z, wf.w);
                    mma_bf16(C[nt], alo, wf.x, wf.y);
                }
                ahi = nh; alo = nl;
            }
#pragma unroll
            for (int nt = 0; nt < 3; nt++) {
                int cbase = (wn * 3 + nt) * 8 + 2 * tg;
                int r0 = wm * 16 + g;
                *(float2*)&Csm[r0 * CSTRIDE + cbase]       = make_float2(C[nt][0], C[nt][1]);
                *(float2*)&Csm[(r0 + 8) * CSTRIDE + cbase] = make_float2(C[nt][2], C[nt][3]);
            }
        } else {
            float Cx[3][4] = {};
            uint4 ahi = Ahi[fb0], alo = Alo[fb0];
#pragma unroll 4
            for (int ks = 0; ks < 32; ks++) {
                uint4 nh, nl;
                if (ks < 31) { nh = Ahi[fb0 + (ks + 1) * 32]; nl = Alo[fb0 + (ks + 1) * 32]; }
#pragma unroll
                for (int nt = 0; nt < 3; nt++) {
                    uint4 wf = Wf[((6 + wn * 3 + nt) * 32 + ks) * 32 + lane];
                    mma_bf16(Cx[nt], ahi, wf.x, wf.y);
                    mma_bf16(Cx[nt], ahi, wf.z, wf.w);
                    mma_bf16(Cx[nt], alo, wf.x, wf.y);
                }
                ahi = nh; alo = nl;
            }
            if (t > 0) {
                int mr = m0 + wm * 16 + g;
#pragma unroll
                for (int nt = 0; nt < 3; nt++) {
                    float2 o0 = make_float2(Cx[nt][0] + bx[nt].x, Cx[nt][1] + bx[nt].y);
                    float2 o1 = make_float2(Cx[nt][2] + bx[nt].x, Cx[nt][3] + bx[nt].y);
                    *(float2*)(g_xg + ((size_t)mr * T_ + (t - 1)) * G3H + gcolv[nt])       = o0;
                    *(float2*)(g_xg + ((size_t)(mr + 8) * T_ + (t - 1)) * G3H + gcolv[nt]) = o1;
                }
            }
        }
        __syncthreads();

        // ---- gate update: 2 outputs per thread ----
#pragma unroll
        for (int i = 0; i < 2; i++) {
            int ml = row2 + i;
            float cr = Csm[ml * CSTRIDE + tx];
            float cz = Csm[ml * CSTRIDE + 16 + tx];
            float cn = Csm[ml * CSTRIDE + 32 + tx];

            float r = sigf(xr[i] + cr + bb0);
            float z = sigf(xz[i] + cz + bb1);
            float n = tanhf(xn[i] + r * (cn + bb2));

            float hnew = (1.0f - z) * n + z * hreg[i];
            hreg[i] = hnew;
            Hsm[ml * HSTRIDE + tx] = hnew;
        }
        __syncthreads();

        pack_hfrag(Hsm, mt, jt, t, tid);

        if (t < T_ - 1) {
#pragma unroll
            for (int i = 0; i < 2; i++) {
                size_t xb = ((size_t)(m0 + row2 + i) * T_ + (t + 1)) * G3H + j;
                xr[i] = g_xg[xb]; xz[i] = g_xg[xb + H_]; xn[i] = g_xg[xb + 2 * H_];
            }
        }

        slot_barrier(mt, jt, bgen + (++genc));
    }

    // ---- tail: xg1[255] from h(255) (fragments in buffer 0) ----
    if (task == 1) {
        const uint4* __restrict__ Ahi = g_hfrag[0][0];
        const uint4* __restrict__ Alo = g_hfrag[0][1];
        float Cx[3][4] = {};
        uint4 ahi = Ahi[fb0], alo = Alo[fb0];
#pragma unroll 4
        for (int ks = 0; ks < 32; ks++) {
            uint4 nh, nl;
            if (ks < 31) { nh = Ahi[fb0 + (ks + 1) * 32]; nl = Alo[fb0 + (ks + 1) * 32]; }
#pragma unroll
            for (int nt = 0; nt < 3; nt++) {
                uint4 wf = Wf[((6 + wn * 3 + nt) * 32 + ks) * 32 + lane];
                mma_bf16(Cx[nt], ahi, wf.x, wf.y);
                mma_bf16(Cx[nt], ahi, wf.z, wf.w);
                mma_bf16(Cx[nt], alo, wf.x, wf.y);
            }
            ahi = nh; alo = nl;
        }
        int mr = m0 + wm * 16 + g;
#pragma unroll
        for (int nt = 0; nt < 3; nt++) {
            float2 o0 = make_float2(Cx[nt][0] + bx[nt].x, Cx[nt][1] + bx[nt].y);
            float2 o1 = make_float2(Cx[nt][2] + bx[nt].x, Cx[nt][3] + bx[nt].y);
            *(float2*)(g_xg + ((size_t)mr * T_ + (T_ - 1)) * G3H + gcolv[nt])       = o0;
            *(float2*)(g_xg + ((size_t)(mr + 8) * T_ + (T_ - 1)) * G3H + gcolv[nt]) = o1;
        }
    }
}

// ---------------------------------------------------------------------------
// Layer-1 recurrence. 512 threads, k-split (two Csm partial buffers).
// ---------------------------------------------------------------------------
__global__ void __launch_bounds__(512, 1) gru_rec1_kernel(
    const float* __restrict__ Whh, const float* __restrict__ bhh)
{
    extern __shared__ char smraw[];
    uint4* Wf   = (uint4*)smraw;                              // 6*32*32 uint4 = 96KB
    float* Csm  = (float*)(smraw + 6 * 32 * 32 * 16);         // 2 x 64 x CSTRIDE
    float* Hsm  = Csm + 2 * 64 * CSTRIDE;

    const int tid  = threadIdx.x;
    const int bid  = blockIdx.x;
    const int jt   = bid & 31, mt = bid >> 5;
    const int m0   = mt * 64, j0 = jt * 16;
    const int w    = tid >> 5, lane = tid & 31;
    const int wm   = (w >> 2) & 3, wn = (w >> 1) & 1, wk = w & 1;
    const int g    = lane >> 2, tg = lane & 3;
    const int m16  = mt * 4 + wm;
    const int tx   = tid & 15;
    const int row2 = (tid >> 4) << 1;
    const int j    = j0 + tx;

    unsigned bgen = 0;
    if (tid < 32) bgen = g_slot[mt][jt][0];
    unsigned genc = 0;

    build_wfrag((uint32_t*)Wf, Whh, j0, tid, 0, 512);

    {
        int idx = (bid & 31) * 512 + tid;
        size_t base = (size_t)mt * 4096;
        uint4 z = make_uint4(0, 0, 0, 0);
        if (idx < 4096)      g_hfrag[0][0][base + idx] = z;
        else if (idx < 8192) g_hfrag[0][1][base + idx - 4096] = z;
    }

    const float bb0 = bhh[j];
    const float bb1 = bhh[H_ + j];
    const float bb2 = bhh[2 * H_ + j];

    float hreg[2] = {0.f, 0.f};

    float xr[2], xz[2], xn[2];
#pragma unroll
    for (int i = 0; i < 2; i++) {
        size_t xb = ((size_t)(m0 + row2 + i) * T_ + 0) * G3H + j;
        xr[i] = g_xg[xb]; xz[i] = g_xg[xb + H_]; xn[i] = g_xg[xb + 2 * H_];
    }

    slot_barrier(mt, jt, bgen + (++genc));

    const int ks0 = wk << 4;
    const size_t fb0 = (size_t)(m16 * 32 + ks0) * 32 + lane;

    for (int t = 0; t < T_; t++) {
        const uint4* __restrict__ Ahi = g_hfrag[t & 1][0];
        const uint4* __restrict__ Alo = g_hfrag[t & 1][1];

        float C[3][4] = {};
        uint4 ahi = Ahi[fb0], alo = Alo[fb0];
#pragma unroll 4
        for (int kk = 0; kk < 16; kk++) {
            uint4 nh, nl;
            if (kk < 15) { nh = Ahi[fb0 + (kk + 1) * 32]; nl = Alo[fb0 + (kk + 1) * 32]; }
            int ks = ks0 + kk;
#pragma unroll
            for (int nt = 0; nt < 3; nt++) {
                uint4 wf = Wf[((wn * 3 + nt) * 32 + ks) * 32 + lane];
                mma_bf16(C[nt], ahi, wf.x, wf.y);
                mma_bf16(C[nt], ahi, wf.z, wf.w);
                mma_bf16(C[nt], alo, wf.x, wf.y);
            }
            ahi = nh; alo = nl;
        }

        float* Cb = Csm + wk * (64 * CSTRIDE);
#pragma unroll
        for (int nt = 0; nt < 3; nt++) {
            int cbase = (wn * 3 + nt) * 8 + 2 * tg;
            int r0 = wm * 16 + g;
            *(float2*)&Cb[r0 * CSTRIDE + cbase]       = make_float2(C[nt][0], C[nt][1]);
            *(float2*)&Cb[(r0 + 8) * CSTRIDE + cbase] = make_float2(C[nt][2], C[nt][3]);
        }
        __syncthreads();

#pragma unroll
        for (int i = 0; i < 2; i++) {
            int ml = row2 + i;
            float cr = Csm[ml * CSTRIDE + tx]      + Csm[64 * CSTRIDE + ml * CSTRIDE + tx];
            float cz = Csm[ml * CSTRIDE + 16 + tx] + Csm[64 * CSTRIDE + ml * CSTRIDE + 16 + tx];
            float cn = Csm[ml * CSTRIDE + 32 + tx] + Csm[64 * CSTRIDE + ml * CSTRIDE + 32 + tx];

            float r = sigf(xr[i] + cr + bb0);
            float z = sigf(xz[i] + cz + bb1);
            float n = tanhf(xn[i] + r * (cn + bb2));

            float hnew = (1.0f - z) * n + z * hreg[i];
            hreg[i] = hnew;
            Hsm[ml * HSTRIDE + tx] = hnew;

            if (t == T_ - 1) {
                g_hT[(size_t)(m0 + ml) * H_ + j] = hnew;
            }
        }
        __syncthreads();

        if (t < T_ - 1) {
            pack_hfrag(Hsm, mt, jt, t, tid);
#pragma unroll
            for (int i = 0; i < 2; i++) {
                size_t xb = ((size_t)(m0 + row2 + i) * T_ + (t + 1)) * G3H + j;
                xr[i] = g_xg[xb]; xz[i] = g_xg[xb + H_]; xn[i] = g_xg[xb + 2 * H_];
            }
            slot_barrier(mt, jt, bgen + (++genc));
        }
    }
}

// ---------------------------------------------------------------------------
// Head: out = relu(relu(hT) @ fc1^T + b1) @ fc2^T + b2
// ---------------------------------------------------------------------------
__global__ void __launch_bounds__(512) head_kernel(
    const float* __restrict__ w1, const float* __restrict__ b1,
    const float* __restrict__ w2, const float* __restrict__ b2,
    float* __restrict__ out)
{
    __shared__ float sh[H_];
    __shared__ float s1[128];
    const int b = blockIdx.x;
    const int tid = threadIdx.x;
    const int w = tid >> 5, lane = tid & 31;

    sh[tid] = fmaxf(g_hT[(size_t)b * H_ + tid], 0.0f);
    __syncthreads();

#pragma unroll
    for (int oo = 0; oo < 8; oo++) {
        int o = w * 8 + oo;
        const float* wr = w1 + (size_t)o * H_;
        float acc = 0.f;
#pragma unroll
        for (int c = 0; c < 4; c++) {
            int k = c * 128 + lane * 4;
            float4 wv = *(const float4*)(wr + k);
            float4 hv = *(const float4*)(&sh[k]);
            acc += wv.x * hv.x + wv.y * hv.y + wv.z * hv.z + wv.w * hv.w;
        }
#pragma unroll
        for (int off = 16; off; off >>= 1)
            acc += __shfl_down_sync(0xFFFFFFFFu, acc, off);
        if (lane == 0) s1[o] = fmaxf(acc + b1[o], 0.0f);
    }
    __syncthreads();

    if (w < 10) {
        const float* wr = w2 + (size_t)w * 128;
        float acc = 0.f;
#pragma unroll
        for (int c = 0; c < 4; c++) {
            int k = lane + c * 32;
            acc += s1[k] * wr[k];
        }
#pragma unroll
        for (int off = 16; off; off >>= 1)
            acc += __shfl_down_sync(0xFFFFFFFFu, acc, off);
        if (lane == 0) out[(size_t)b * 10 + w] = acc + b2[w];
    }
}

// ---------------------------------------------------------------------------
// Launch
// ---------------------------------------------------------------------------
extern "C" void kernel_launch(void* const* d_in, const int* in_sizes, int n_in,
                              void* d_out, int out_size)
{
    const float* x    = (const float*)d_in[0];
    const float* Wih0 = (const float*)d_in[1];
    const float* Whh0 = (const float*)d_in[2];
    const float* bih0 = (const float*)d_in[3];
    const float* bhh0 = (const float*)d_in[4];
    const float* Wih1 = (const float*)d_in[5];
    const float* Whh1 = (const float*)d_in[6];
    const float* bih1 = (const float*)d_in[7];
    const float* bhh1 = (const float*)d_in[8];
    const float* fc1w = (const float*)d_in[9];
    const float* fc1b = (const float*)d_in[10];
    const float* fc2w = (const float*)d_in[11];
    const float* fc2b = (const float*)d_in[12];
    float* out = (float*)d_out;

    float* xg_ptr = nullptr;
    cudaGetSymbolAddress((void**)&xg_ptr, g_xg);

    const int rec0_smem = 12 * 32 * 32 * 16 + (64 * CSTRIDE + 64 * HSTRIDE) * 4;       // 213760
    const int rec1_smem = 6 * 32 * 32 * 16 + (2 * 64 * CSTRIDE + 64 * HSTRIDE) * 4;    // 128256
    cudaFuncSetAttribute((const void*)gru_rec0_fused_kernel,
                         cudaFuncAttributeMaxDynamicSharedMemorySize, rec0_smem);
    cudaFuncSetAttribute((const void*)gru_rec1_kernel,
                         cudaFuncAttributeMaxDynamicSharedMemorySize, rec1_smem);

    dim3 gemm_grid(G3H / 128, BT / 128);  // (12, 512)

    // Phase 1: xg0 = x @ W_ih0^T + b_ih0   (K = 128)
    gemm_tf32_kernel<<<gemm_grid, 256>>>(x, Wih0, bih0, D_, xg_ptr);

    // Phase 2: fused layer-0 recurrence + layer-1 input projection
    gru_rec0_fused_kernel<<<128, 512, rec0_smem>>>(Whh0, bhh0, Wih1, bih1);

    // Phase 3: layer-1 recurrence
    gru_rec1_kernel<<<128, 512, rec1_smem>>>(Whh1, bhh1);

    // Phase 4: MLP head
    head_kernel<<<B_, 512>>>(fc1w, fc1b, fc2w, fc2b, out);
}

// round 9
// speedup vs baseline: 1.4833x; 1.0066x over previous
#include <cuda_runtime.h>
#include <cuda_bf16.h>
#include <math.h>
#include <stdint.h>

// Problem dims (fixed by the dataset)
#define B_   256
#define T_   256
#define D_   128
#define H_   512
#define G3H  1536
#define BT   (B_ * T_)

// ---------------------------------------------------------------------------
// Scratch (static device allocations; harness forbids cudaMalloc)
// ---------------------------------------------------------------------------
__device__ float g_xg[(size_t)BT * G3H];   // xg0, overwritten in-place by xg1
__device__ float g_hT[B_ * H_];            // final hidden of layer 1
// h in A-fragment order, bf16 hi/lo, double buffered
__device__ uint4 g_hfrag[2][2][16 * 32 * 32];

// Slot barrier: each block owns one 128B line; monotonic gens, snapshot at
// kernel start (only the owner writes its slot; all blocks of a group store
// the same number of gens per kernel) -> replay-safe.
__device__ volatile unsigned g_slot[4][32][32];

__device__ __forceinline__ void slot_barrier(int grp, int blk, unsigned gen) {
    __syncthreads();
    if (threadIdx.x == 0) {
        __threadfence();                    // release own writes
        g_slot[grp][blk][0] = gen;
    }
    if (threadIdx.x < 32) {
        while ((int)(g_slot[grp][threadIdx.x][0] - gen) < 0) { }
        __threadfence();                    // acquire
    }
    __syncthreads();
}

// ---------------------------------------------------------------------------
// math helpers
// ---------------------------------------------------------------------------
__device__ __forceinline__ uint32_t f2tf(float f) {
    uint32_t u;
    asm("cvt.rna.tf32.f32 %0, %1;" : "=r"(u) : "f"(f));
    return u;
}

__device__ __forceinline__ void mma_tf32(float* c, const uint32_t* a, const uint32_t* b) {
    asm volatile(
        "mma.sync.aligned.m16n8k8.row.col.f32.tf32.tf32.f32 "
        "{%0,%1,%2,%3}, {%4,%5,%6,%7}, {%8,%9}, {%0,%1,%2,%3};\n"
        : "+f"(c[0]), "+f"(c[1]), "+f"(c[2]), "+f"(c[3])
        : "r"(a[0]), "r"(a[1]), "r"(a[2]), "r"(a[3]), "r"(b[0]), "r"(b[1]));
}

__device__ __forceinline__ void mma_bf16(float* c, const uint4& a, uint32_t b0, uint32_t b1) {
    asm volatile(
        "mma.sync.aligned.m16n8k16.row.col.f32.bf16.bf16.f32 "
        "{%0,%1,%2,%3}, {%4,%5,%6,%7}, {%8,%9}, {%0,%1,%2,%3};\n"
        : "+f"(c[0]), "+f"(c[1]), "+f"(c[2]), "+f"(c[3])
        : "r"(a.x), "r"(a.y), "r"(a.z), "r"(a.w), "r"(b0), "r"(b1));
}

__device__ __forceinline__ uint32_t pack2_bf16(float e0, float e1) {
    __nv_bfloat162 t = __floats2bfloat162_rn(e0, e1);  // .x = low half
    return *(uint32_t*)&t;
}

__device__ __forceinline__ float sigf(float x) {
    return 1.0f / (1.0f + __expf(-x));
}

// Build bf16 hi/lo B-fragments for a 48-col x 512-k weight tile with the
// GATE-LOCAL column order: logical col n = wn*24 + gate*8 + jl
// -> weight row gate*H + j0 + wn*8 + jl. This puts all 3 gates of a hidden
// unit into the SAME C-fragment thread, so the GRU gate update runs in the
// MMA thread's registers (no smem exchange).
__device__ __forceinline__ void build_wfrag2(
    uint32_t* Wu, const float* __restrict__ Wsrc, int j0, int tid, int slot_off, int nthreads)
{
    for (int idx = tid; idx < 48 * 256; idx += nthreads) {
        int n  = idx >> 8;
        int k  = (idx & 255) << 1;
        int wn_t = n / 24;
        int rem  = n - wn_t * 24;
        int gate = rem >> 3, jl = rem & 7;
        const float* wrow = Wsrc + ((size_t)(gate * H_ + j0 + wn_t * 8 + jl)) * H_;
        float w0 = wrow[k], w1 = wrow[k + 1];
        float h0 = __bfloat162float(__float2bfloat16(w0));
        float h1 = __bfloat162float(__float2bfloat16(w1));
        uint32_t hi = pack2_bf16(h0, h1);
        uint32_t lo = pack2_bf16(w0 - h0, w1 - h1);
        int nt = (n >> 3) + slot_off;
        int ks = k >> 4, kr = k & 15;
        int rr = (kr >= 8) ? 1 : 0;
        int lw = (n & 7) * 4 + ((kr >> 1) & 3);
        int base = (((nt * 32 + ks) * 32 + lw) << 2);
        Wu[base + rr]     = hi;
        Wu[base + 2 + rr] = lo;
    }
}

// 16x48 (per warp) GEMM over npairs*2 k-slices: bf16x3 with ks-parity-split
// accumulators (6 independent HMMA chains), register double-buffered A-frags.
__device__ __forceinline__ void gemm48(
    float C[3][4], const uint4* __restrict__ Wf, int slot, int koff,
    const uint4* __restrict__ Ahi, const uint4* __restrict__ Alo,
    size_t fb0, int lane, int npairs)
{
    float Ca[3][4] = {}, Cb[3][4] = {};
    uint4 ah0 = Ahi[fb0],      al0 = Alo[fb0];
    uint4 ah1 = Ahi[fb0 + 32], al1 = Alo[fb0 + 32];
#pragma unroll 4
    for (int kp = 0; kp < npairs; kp++) {
        uint4 nh0, nl0, nh1, nl1;
        if (kp < npairs - 1) {
            nh0 = Ahi[fb0 + (2 * kp + 2) * 32]; nl0 = Alo[fb0 + (2 * kp + 2) * 32];
            nh1 = Ahi[fb0 + (2 * kp + 3) * 32]; nl1 = Alo[fb0 + (2 * kp + 3) * 32];
        }
#pragma unroll
        for (int nt = 0; nt < 3; nt++) {
            uint4 w0 = Wf[((slot + nt) * 32 + koff + 2 * kp) * 32 + lane];
            mma_bf16(Ca[nt], ah0, w0.x, w0.y);
            mma_bf16(Ca[nt], ah0, w0.z, w0.w);
            mma_bf16(Ca[nt], al0, w0.x, w0.y);
            uint4 w1 = Wf[((slot + nt) * 32 + koff + 2 * kp + 1) * 32 + lane];
            mma_bf16(Cb[nt], ah1, w1.x, w1.y);
            mma_bf16(Cb[nt], ah1, w1.z, w1.w);
            mma_bf16(Cb[nt], al1, w1.x, w1.y);
        }
        ah0 = nh0; al0 = nl0; ah1 = nh1; al1 = nl1;
    }
#pragma unroll
    for (int nt = 0; nt < 3; nt++)
#pragma unroll
        for (int i = 0; i < 4; i++)
            C[nt][i] = Ca[nt][i] + Cb[nt][i];
}

// ---------------------------------------------------------------------------
// tf32 tensor-core GEMM (phase 1): xg0 = x @ Wih0^T + bih0
// ---------------------------------------------------------------------------
__global__ void __launch_bounds__(256) gemm_tf32_kernel(
    const float* __restrict__ A, const float* __restrict__ W,
    const float* __restrict__ bias, int K, float* __restrict__ C)
{
    __shared__ uint32_t As[128][36];
    __shared__ uint32_t Bs[128][36];

    const int tid  = threadIdx.x;
    const int m0   = blockIdx.y * 128;
    const int n0   = blockIdx.x * 128;
    const int warp = tid >> 5, lane = tid & 31;
    const int wm = warp >> 2, wn = warp & 3;
    const int g  = lane >> 2, tg = lane & 3;

    float acc[4][4][4] = {};

    for (int k0 = 0; k0 < K; k0 += 32) {
#pragma unroll
        for (int r = 0; r < 4; r++) {
            int f   = tid + (r << 8);
            int row = f >> 3;
            int c4  = (f & 7) << 2;
            float4 va = *(const float4*)(A + (size_t)(m0 + row) * K + k0 + c4);
            As[row][c4 + 0] = f2tf(va.x);
            As[row][c4 + 1] = f2tf(va.y);
            As[row][c4 + 2] = f2tf(va.z);
            As[row][c4 + 3] = f2tf(va.w);
            float4 vb = *(const float4*)(W + (size_t)(n0 + row) * K + k0 + c4);
            Bs[row][c4 + 0] = f2tf(vb.x);
            Bs[row][c4 + 1] = f2tf(vb.y);
            Bs[row][c4 + 2] = f2tf(vb.z);
            Bs[row][c4 + 3] = f2tf(vb.w);
        }
        __syncthreads();

#pragma unroll
        for (int s = 0; s < 4; s++) {
            const int kb = s << 3;
            uint32_t a[4][4], b[4][2];
#pragma unroll
            for (int i = 0; i < 4; i++) {
                int r0 = wm * 64 + i * 16 + g;
                a[i][0] = As[r0][kb + tg];
                a[i][1] = As[r0 + 8][kb + tg];
                a[i][2] = As[r0][kb + tg + 4];
                a[i][3] = As[r0 + 8][kb + tg + 4];
            }
#pragma unroll
            for (int jx = 0; jx < 4; jx++) {
                int c = wn * 32 + jx * 8 + g;
                b[jx][0] = Bs[c][kb + tg];
                b[jx][1] = Bs[c][kb + tg + 4];
            }
#pragma unroll
            for (int i = 0; i < 4; i++)
#pragma unroll
                for (int jx = 0; jx < 4; jx++)
                    mma_tf32(acc[i][jx], a[i], b[jx]);
        }
        __syncthreads();
    }

#pragma unroll
    for (int i = 0; i < 4; i++) {
        int r0 = m0 + wm * 64 + i * 16 + g;
#pragma unroll
        for (int jx = 0; jx < 4; jx++) {
            int col = n0 + wn * 32 + jx * 8 + tg * 2;
            float2 bv = *(const float2*)(bias + col);
            float2 o0 = make_float2(acc[i][jx][0] + bv.x, acc[i][jx][1] + bv.y);
            float2 o1 = make_float2(acc[i][jx][2] + bv.x, acc[i][jx][3] + bv.y);
            *(float2*)(C + (size_t)r0 * G3H + col)       = o0;
            *(float2*)(C + (size_t)(r0 + 8) * G3H + col) = o1;
        }
    }
}

// ---------------------------------------------------------------------------
// FUSED layer-0 recurrence + layer-1 input projection. 512 threads.
// Warps 0-7 (task 0): rec GEMM + gate math IN REGISTERS + direct frag stores.
// Warps 8-15 (task 1): xg1 GEMM, writes g_xg from fragments.
// No intra-window __syncthreads (only inside the slot barrier).
// ---------------------------------------------------------------------------
__global__ void __launch_bounds__(512, 1) gru_rec0_fused_kernel(
    const float* __restrict__ Whh, const float* __restrict__ bhh,
    const float* __restrict__ Wih1, const float* __restrict__ bih1)
{
    extern __shared__ char smraw[];
    uint4* Wf = (uint4*)smraw;   // 12*32*32 uint4 = 192KB

    const int tid = threadIdx.x;
    const int bid = blockIdx.x;
    const int jt = bid & 31, mt = bid >> 5;
    const int m0 = mt * 64, j0 = jt * 16;
    const int w = tid >> 5, lane = tid & 31;
    const int task = w >> 3, wsub = w & 7;
    const int wm = wsub >> 1, wn = wsub & 1;
    const int g = lane >> 2, tg = lane & 3;
    const int m16 = mt * 4 + wm;

    unsigned bgen = 0;
    if (tid < 32) bgen = g_slot[mt][jt][0];
    unsigned genc = 0;

    build_wfrag2((uint32_t*)Wf, Whh,  j0, tid, 0, 512);
    build_wfrag2((uint32_t*)Wf, Wih1, j0, tid, 6, 512);

    // Zero h fragment buffer 0 for THIS group only
    {
        int idx = (bid & 31) * 512 + tid;
        size_t base = (size_t)mt * 4096;
        uint4 z = make_uint4(0, 0, 0, 0);
        if (idx < 4096)      g_hfrag[0][0][base + idx] = z;
        else if (idx < 8192) g_hfrag[0][1][base + idx - 4096] = z;
    }

    const int jc    = j0 + wn * 8 + 2 * tg;   // this thread's first j column
    const int mrow0 = m0 + wm * 16 + g;       // this thread's rows
    const int mrow1 = mrow0 + 8;

    float br[2], bz[2], bn_[2];
    float2 bx[3];
    if (task == 0) {
        br[0]  = bhh[jc];           br[1]  = bhh[jc + 1];
        bz[0]  = bhh[H_ + jc];      bz[1]  = bhh[H_ + jc + 1];
        bn_[0] = bhh[2 * H_ + jc];  bn_[1] = bhh[2 * H_ + jc + 1];
    } else {
#pragma unroll
        for (int nt = 0; nt < 3; nt++)
            bx[nt] = make_float2(bih1[nt * H_ + jc], bih1[nt * H_ + jc + 1]);
    }

    float hreg[4] = {0.f, 0.f, 0.f, 0.f};
    float xr[4], xz[4], xn[4];

    auto prefetch_xg = [&](int tt) {
        size_t b0 = ((size_t)mrow0 * T_ + tt) * G3H + jc;
        size_t b1 = ((size_t)mrow1 * T_ + tt) * G3H + jc;
        float2 v;
        v = *(const float2*)(g_xg + b0);           xr[0] = v.x; xr[1] = v.y;
        v = *(const float2*)(g_xg + b0 + H_);      xz[0] = v.x; xz[1] = v.y;
        v = *(const float2*)(g_xg + b0 + 2 * H_);  xn[0] = v.x; xn[1] = v.y;
        v = *(const float2*)(g_xg + b1);           xr[2] = v.x; xr[3] = v.y;
        v = *(const float2*)(g_xg + b1 + H_);      xz[2] = v.x; xz[3] = v.y;
        v = *(const float2*)(g_xg + b1 + 2 * H_);  xn[2] = v.x; xn[3] = v.y;
    };
    if (task == 0) prefetch_xg(0);

    slot_barrier(mt, jt, bgen + (++genc));

    const size_t fb0 = (size_t)(m16 * 32) * 32 + lane;
    const size_t sb  = ((size_t)(m16 * 32) + jt) * 32 + lane;

    for (int t = 0; t < T_; t++) {
        const uint4* __restrict__ Ahi = g_hfrag[t & 1][0];
        const uint4* __restrict__ Alo = g_hfrag[t & 1][1];

        if (task == 0) {
            float C[3][4];
            gemm48(C, Wf, wn * 3, 0, Ahi, Alo, fb0, lane, 16);

            float hv[4];
#pragma unroll
            for (int i = 0; i < 4; i++) {
                float r  = sigf(xr[i] + C[0][i] + br[i & 1]);
                float z  = sigf(xz[i] + C[1][i] + bz[i & 1]);
                float nv = tanhf(xn[i] + r * (C[2][i] + bn_[i & 1]));
                float h  = (1.0f - z) * nv + z * hreg[i];
                hreg[i] = h; hv[i] = h;
            }
            float fh[4], fl[4];
#pragma unroll
            for (int q = 0; q < 4; q++) {
                fh[q] = __bfloat162float(__float2bfloat16(hv[q]));
                fl[q] = hv[q] - fh[q];
            }
            uint2 hiu = make_uint2(pack2_bf16(fh[0], fh[1]), pack2_bf16(fh[2], fh[3]));
            uint2 lou = make_uint2(pack2_bf16(fl[0], fl[1]), pack2_bf16(fl[2], fl[3]));
            const int nb = (t + 1) & 1;
            ((uint2*)&g_hfrag[nb][0][sb])[wn] = hiu;
            ((uint2*)&g_hfrag[nb][1][sb])[wn] = lou;

            if (t < T_ - 1) prefetch_xg(t + 1);
        } else if (t > 0) {
            float C[3][4];
            gemm48(C, Wf, 6 + wn * 3, 0, Ahi, Alo, fb0, lane, 16);
#pragma unroll
            for (int nt = 0; nt < 3; nt++) {
                size_t o0 = ((size_t)mrow0 * T_ + (t - 1)) * G3H + nt * H_ + jc;
                size_t o1 = ((size_t)mrow1 * T_ + (t - 1)) * G3H + nt * H_ + jc;
                *(float2*)(g_xg + o0) = make_float2(C[nt][0] + bx[nt].x, C[nt][1] + bx[nt].y);
                *(float2*)(g_xg + o1) = make_float2(C[nt][2] + bx[nt].x, C[nt][3] + bx[nt].y);
            }
        }

        slot_barrier(mt, jt, bgen + (++genc));
    }

    // tail: xg1[255] from h(255) (fragments in buffer 0)
    if (task == 1) {
        float C[3][4];
        gemm48(C, Wf, 6 + wn * 3, 0, g_hfrag[0][0], g_hfrag[0][1], fb0, lane, 16);
#pragma unroll
        for (int nt = 0; nt < 3; nt++) {
            size_t o0 = ((size_t)mrow0 * T_ + (T_ - 1)) * G3H + nt * H_ + jc;
            size_t o1 = ((size_t)mrow1 * T_ + (T_ - 1)) * G3H + nt * H_ + jc;
            *(float2*)(g_xg + o0) = make_float2(C[nt][0] + bx[nt].x, C[nt][1] + bx[nt].y);
            *(float2*)(g_xg + o1) = make_float2(C[nt][2] + bx[nt].x, C[nt][3] + bx[nt].y);
        }
    }
}

// ---------------------------------------------------------------------------
// Layer-1 recurrence. 512 threads, k-split: wk=1 computes the upper k-half
// and exchanges partials via a small conflict-free scalar smem buffer; wk=0
// adds, does gate math in registers, stores frags / hT directly.
// ---------------------------------------------------------------------------
__global__ void __launch_bounds__(512, 1) gru_rec1_kernel(
    const float* __restrict__ Whh, const float* __restrict__ bhh)
{
    extern __shared__ char smraw[];
    uint4* Wf  = (uint4*)smraw;                        // 96KB
    float* Psm = (float*)(smraw + 6 * 32 * 32 * 16);   // [12][256] = 12KB

    const int tid = threadIdx.x;
    const int bid = blockIdx.x;
    const int jt = bid & 31, mt = bid >> 5;
    const int m0 = mt * 64, j0 = jt * 16;
    const int w = tid >> 5, lane = tid & 31;
    const int wm = (w >> 2) & 3, wn = (w >> 1) & 1, wk = w & 1;
    const int g = lane >> 2, tg = lane & 3;
    const int m16 = mt * 4 + wm;

    unsigned bgen = 0;
    if (tid < 32) bgen = g_slot[mt][jt][0];
    unsigned genc = 0;

    build_wfrag2((uint32_t*)Wf, Whh, j0, tid, 0, 512);

    {
        int idx = (bid & 31) * 512 + tid;
        size_t base = (size_t)mt * 4096;
        uint4 z = make_uint4(0, 0, 0, 0);
        if (idx < 4096)      g_hfrag[0][0][base + idx] = z;
        else if (idx < 8192) g_hfrag[0][1][base + idx - 4096] = z;
    }

    const int jc    = j0 + wn * 8 + 2 * tg;
    const int mrow0 = m0 + wm * 16 + g;
    const int mrow1 = mrow0 + 8;
    const int pslot = (wm * 2 + wn) * 32 + lane;   // 0..255

    float br[2], bz[2], bn_[2];
    br[0]  = bhh[jc];           br[1]  = bhh[jc + 1];
    bz[0]  = bhh[H_ + jc];      bz[1]  = bhh[H_ + jc + 1];
    bn_[0] = bhh[2 * H_ + jc];  bn_[1] = bhh[2 * H_ + jc + 1];

    float hreg[4] = {0.f, 0.f, 0.f, 0.f};
    float xr[4], xz[4], xn[4];

    auto prefetch_xg = [&](int tt) {
        size_t b0 = ((size_t)mrow0 * T_ + tt) * G3H + jc;
        size_t b1 = ((size_t)mrow1 * T_ + tt) * G3H + jc;
        float2 v;
        v = *(const float2*)(g_xg + b0);           xr[0] = v.x; xr[1] = v.y;
        v = *(const float2*)(g_xg + b0 + H_);      xz[0] = v.x; xz[1] = v.y;
        v = *(const float2*)(g_xg + b0 + 2 * H_);  xn[0] = v.x; xn[1] = v.y;
        v = *(const float2*)(g_xg + b1);           xr[2] = v.x; xr[3] = v.y;
        v = *(const float2*)(g_xg + b1 + H_);      xz[2] = v.x; xz[3] = v.y;
        v = *(const float2*)(g_xg + b1 + 2 * H_);  xn[2] = v.x; xn[3] = v.y;
    };
    if (wk == 0) prefetch_xg(0);

    slot_barrier(mt, jt, bgen + (++genc));

    const size_t fb0 = (size_t)(m16 * 32 + wk * 16) * 32 + lane;
    const size_t sb  = ((size_t)(m16 * 32) + jt) * 32 + lane;

    for (int t = 0; t < T_; t++) {
        const uint4* __restrict__ Ahi = g_hfrag[t & 1][0];
        const uint4* __restrict__ Alo = g_hfrag[t & 1][1];

        float C[3][4];
        gemm48(C, Wf, wn * 3, wk * 16, Ahi, Alo, fb0, lane, 8);

        if (wk == 1) {
#pragma unroll
            for (int nt = 0; nt < 3; nt++)
#pragma unroll
                for (int i = 0; i < 4; i++)
                    Psm[(nt * 4 + i) * 256 + pslot] = C[nt][i];
        }
        __syncthreads();

        if (wk == 0) {
            float hv[4];
#pragma unroll
            for (int i = 0; i < 4; i++) {
                float cr = C[0][i] + Psm[(0 + i) * 256 + pslot];
                float cz = C[1][i] + Psm[(4 + i) * 256 + pslot];
                float cn = C[2][i] + Psm[(8 + i) * 256 + pslot];
                float r  = sigf(xr[i] + cr + br[i & 1]);
                float z  = sigf(xz[i] + cz + bz[i & 1]);
                float nv = tanhf(xn[i] + r * (cn + bn_[i & 1]));
                float h  = (1.0f - z) * nv + z * hreg[i];
                hreg[i] = h; hv[i] = h;
            }
            if (t == T_ - 1) {
                *(float2*)(g_hT + (size_t)mrow0 * H_ + jc) = make_float2(hv[0], hv[1]);
                *(float2*)(g_hT + (size_t)mrow1 * H_ + jc) = make_float2(hv[2], hv[3]);
            } else {
                float fh[4], fl[4];
#pragma unroll
                for (int q = 0; q < 4; q++) {
                    fh[q] = __bfloat162float(__float2bfloat16(hv[q]));
                    fl[q] = hv[q] - fh[q];
                }
                uint2 hiu = make_uint2(pack2_bf16(fh[0], fh[1]), pack2_bf16(fh[2], fh[3]));
                uint2 lou = make_uint2(pack2_bf16(fl[0], fl[1]), pack2_bf16(fl[2], fl[3]));
                const int nb = (t + 1) & 1;
                ((uint2*)&g_hfrag[nb][0][sb])[wn] = hiu;
                ((uint2*)&g_hfrag[nb][1][sb])[wn] = lou;
                prefetch_xg(t + 1);
            }
        }

        if (t < T_ - 1) slot_barrier(mt, jt, bgen + (++genc));
    }
}

// ---------------------------------------------------------------------------
// Head: out = relu(relu(hT) @ fc1^T + b1) @ fc2^T + b2
// ---------------------------------------------------------------------------
__global__ void __launch_bounds__(512) head_kernel(
    const float* __restrict__ w1, const float* __restrict__ b1,
    const float* __restrict__ w2, const float* __restrict__ b2,
    float* __restrict__ out)
{
    __shared__ float sh[H_];
    __shared__ float s1[128];
    const int b = blockIdx.x;
    const int tid = threadIdx.x;
    const int w = tid >> 5, lane = tid & 31;

    sh[tid] = fmaxf(g_hT[(size_t)b * H_ + tid], 0.0f);
    __syncthreads();

#pragma unroll
    for (int oo = 0; oo < 8; oo++) {
        int o = w * 8 + oo;
        const float* wr = w1 + (size_t)o * H_;
        float acc = 0.f;
#pragma unroll
        for (int c = 0; c < 4; c++) {
            int k = c * 128 + lane * 4;
            float4 wv = *(const float4*)(wr + k);
            float4 hv = *(const float4*)(&sh[k]);
            acc += wv.x * hv.x + wv.y * hv.y + wv.z * hv.z + wv.w * hv.w;
        }
#pragma unroll
        for (int off = 16; off; off >>= 1)
            acc += __shfl_down_sync(0xFFFFFFFFu, acc, off);
        if (lane == 0) s1[o] = fmaxf(acc + b1[o], 0.0f);
    }
    __syncthreads();

    if (w < 10) {
        const float* wr = w2 + (size_t)w * 128;
        float acc = 0.f;
#pragma unroll
        for (int c = 0; c < 4; c++) {
            int k = lane + c * 32;
            acc += s1[k] * wr[k];
        }
#pragma unroll
        for (int off = 16; off; off >>= 1)
            acc += __shfl_down_sync(0xFFFFFFFFu, acc, off);
        if (lane == 0) out[(size_t)b * 10 + w] = acc + b2[w];
    }
}

// ---------------------------------------------------------------------------
// Launch
// ---------------------------------------------------------------------------
extern "C" void kernel_launch(void* const* d_in, const int* in_sizes, int n_in,
                              void* d_out, int out_size)
{
    const float* x    = (const float*)d_in[0];
    const float* Wih0 = (const float*)d_in[1];
    const float* Whh0 = (const float*)d_in[2];
    const float* bih0 = (const float*)d_in[3];
    const float* bhh0 = (const float*)d_in[4];
    const float* Wih1 = (const float*)d_in[5];
    const float* Whh1 = (const float*)d_in[6];
    const float* bih1 = (const float*)d_in[7];
    const float* bhh1 = (const float*)d_in[8];
    const float* fc1w = (const float*)d_in[9];
    const float* fc1b = (const float*)d_in[10];
    const float* fc2w = (const float*)d_in[11];
    const float* fc2b = (const float*)d_in[12];
    float* out = (float*)d_out;

    float* xg_ptr = nullptr;
    cudaGetSymbolAddress((void**)&xg_ptr, g_xg);

    const int rec0_smem = 12 * 32 * 32 * 16;                 // 192KB
    const int rec1_smem = 6 * 32 * 32 * 16 + 12 * 256 * 4;   // 96KB + 12KB
    cudaFuncSetAttribute((const void*)gru_rec0_fused_kernel,
                         cudaFuncAttributeMaxDynamicSharedMemorySize, rec0_smem);
    cudaFuncSetAttribute((const void*)gru_rec1_kernel,
                         cudaFuncAttributeMaxDynamicSharedMemorySize, rec1_smem);

    dim3 gemm_grid(G3H / 128, BT / 128);  // (12, 512)

    // Phase 1: xg0 = x @ W_ih0^T + b_ih0   (K = 128)
    gemm_tf32_kernel<<<gemm_grid, 256>>>(x, Wih0, bih0, D_, xg_ptr);

    // Phase 2: fused layer-0 recurrence + layer-1 input projection
    gru_rec0_fused_kernel<<<128, 512, rec0_smem>>>(Whh0, bhh0, Wih1, bih1);

    // Phase 3: layer-1 recurrence
    gru_rec1_kernel<<<128, 512, rec1_smem>>>(Whh1, bhh1);

    // Phase 4: MLP head
    head_kernel<<<B_, 512>>>(fc1w, fc1b, fc2w, fc2b, out);
}

// round 10
// speedup vs baseline: 1.7149x; 1.1561x over previous
#include <cuda_runtime.h>
#include <cuda_bf16.h>
#include <math.h>
#include <stdint.h>

// Problem dims (fixed by the dataset)
#define B_   256
#define T_   256
#define D_   128
#define H_   512
#define G3H  1536
#define BT   (B_ * T_)

// ---------------------------------------------------------------------------
// Scratch (static device allocations; harness forbids cudaMalloc)
// ---------------------------------------------------------------------------
__device__ float g_xg[(size_t)BT * G3H];   // xg0 only (no xg1 round-trip anymore)
__device__ float g_hT[B_ * H_];            // final hidden of layer 1
__device__ uint4 g_wfrag1[32 * 6144];      // Wih1 fragments per jt (3MB, L2-resident)
// h fragments, A-layout, bf16 hi/lo, double buffered
__device__ uint4 g_h0frag[2][2][16 * 32 * 32];
__device__ uint4 g_h1frag[2][2][16 * 32 * 32];

// Slot barrier: each block owns one 128B line; monotonic gens, snapshot at
// kernel start (only the owner writes its slot; all blocks of a group store
// the same number of gens per kernel) -> replay-safe.
__device__ volatile unsigned g_slot[4][32][32];

__device__ __forceinline__ void slot_barrier(int grp, int blk, unsigned gen) {
    __syncthreads();
    if (threadIdx.x == 0) {
        __threadfence();                    // release own writes
        g_slot[grp][blk][0] = gen;
    }
    if (threadIdx.x < 32) {
        while ((int)(g_slot[grp][threadIdx.x][0] - gen) < 0) { }
        __threadfence();                    // acquire
    }
    __syncthreads();
}

// ---------------------------------------------------------------------------
// math helpers
// ---------------------------------------------------------------------------
__device__ __forceinline__ uint32_t f2tf(float f) {
    uint32_t u;
    asm("cvt.rna.tf32.f32 %0, %1;" : "=r"(u) : "f"(f));
    return u;
}

__device__ __forceinline__ void mma_tf32(float* c, const uint32_t* a, const uint32_t* b) {
    asm volatile(
        "mma.sync.aligned.m16n8k8.row.col.f32.tf32.tf32.f32 "
        "{%0,%1,%2,%3}, {%4,%5,%6,%7}, {%8,%9}, {%0,%1,%2,%3};\n"
        : "+f"(c[0]), "+f"(c[1]), "+f"(c[2]), "+f"(c[3])
        : "r"(a[0]), "r"(a[1]), "r"(a[2]), "r"(a[3]), "r"(b[0]), "r"(b[1]));
}

__device__ __forceinline__ void mma_bf16(float* c, const uint4& a, uint32_t b0, uint32_t b1) {
    asm volatile(
        "mma.sync.aligned.m16n8k16.row.col.f32.bf16.bf16.f32 "
        "{%0,%1,%2,%3}, {%4,%5,%6,%7}, {%8,%9}, {%0,%1,%2,%3};\n"
        : "+f"(c[0]), "+f"(c[1]), "+f"(c[2]), "+f"(c[3])
        : "r"(a.x), "r"(a.y), "r"(a.z), "r"(a.w), "r"(b0), "r"(b1));
}

__device__ __forceinline__ uint32_t pack2_bf16(float e0, float e1) {
    __nv_bfloat162 t = __floats2bfloat162_rn(e0, e1);  // .x = low half
    return *(uint32_t*)&t;
}

__device__ __forceinline__ float sigf(float x) {
    return 1.0f / (1.0f + __expf(-x));
}

// Build bf16 hi/lo B-fragments for a 48-col x 512-k weight tile with the
// GATE-LOCAL column order: logical col n = wn*24 + gate*8 + jl
// -> weight row gate*H + j0 + wn*8 + jl. All 3 gates of a hidden unit land in
// the SAME C-fragment thread (gate math in registers, no smem exchange).
__device__ __forceinline__ void build_wfrag2(
    uint32_t* Wu, const float* __restrict__ Wsrc, int j0, int tid, int slot_off, int nthreads)
{
    for (int idx = tid; idx < 48 * 256; idx += nthreads) {
        int n  = idx >> 8;
        int k  = (idx & 255) << 1;
        int wn_t = n / 24;
        int rem  = n - wn_t * 24;
        int gate = rem >> 3, jl = rem & 7;
        const float* wrow = Wsrc + ((size_t)(gate * H_ + j0 + wn_t * 8 + jl)) * H_;
        float w0 = wrow[k], w1 = wrow[k + 1];
        float h0 = __bfloat162float(__float2bfloat16(w0));
        float h1 = __bfloat162float(__float2bfloat16(w1));
        uint32_t hi = pack2_bf16(h0, h1);
        uint32_t lo = pack2_bf16(w0 - h0, w1 - h1);
        int nt = (n >> 3) + slot_off;
        int ks = k >> 4, kr = k & 15;
        int rr = (kr >= 8) ? 1 : 0;
        int lw = (n & 7) * 4 + ((kr >> 1) & 3);
        int base = (((nt * 32 + ks) * 32 + lw) << 2);
        Wu[base + rr]     = hi;
        Wu[base + 2 + rr] = lo;
    }
}

// Setup: Wih1 fragments to an L2-resident global table (slots 0..5 per jt)
__global__ void __launch_bounds__(512) build_wih1_kernel(const float* __restrict__ Wih1) {
    int jt = blockIdx.x;
    build_wfrag2((uint32_t*)(g_wfrag1 + (size_t)jt * 6144), Wih1, jt * 16, threadIdx.x, 0, 512);
}

// 16x48 (per warp) GEMM over npairs*2 k-slices: bf16x3 with ks-parity-split
// accumulators (6 independent HMMA chains), register double-buffered A-frags.
__device__ __forceinline__ void gemm48(
    float C[3][4], const uint4* __restrict__ Wf, int slot, int koff,
    const uint4* __restrict__ Ahi, const uint4* __restrict__ Alo,
    size_t fb0, int lane, int npairs)
{
    float Ca[3][4] = {}, Cb[3][4] = {};
    uint4 ah0 = Ahi[fb0],      al0 = Alo[fb0];
    uint4 ah1 = Ahi[fb0 + 32], al1 = Alo[fb0 + 32];
#pragma unroll 4
    for (int kp = 0; kp < npairs; kp++) {
        uint4 nh0, nl0, nh1, nl1;
        if (kp < npairs - 1) {
            nh0 = Ahi[fb0 + (2 * kp + 2) * 32]; nl0 = Alo[fb0 + (2 * kp + 2) * 32];
            nh1 = Ahi[fb0 + (2 * kp + 3) * 32]; nl1 = Alo[fb0 + (2 * kp + 3) * 32];
        }
#pragma unroll
        for (int nt = 0; nt < 3; nt++) {
            uint4 w0 = Wf[((slot + nt) * 32 + koff + 2 * kp) * 32 + lane];
            mma_bf16(Ca[nt], ah0, w0.x, w0.y);
            mma_bf16(Ca[nt], ah0, w0.z, w0.w);
            mma_bf16(Ca[nt], al0, w0.x, w0.y);
            uint4 w1 = Wf[((slot + nt) * 32 + koff + 2 * kp + 1) * 32 + lane];
            mma_bf16(Cb[nt], ah1, w1.x, w1.y);
            mma_bf16(Cb[nt], ah1, w1.z, w1.w);
            mma_bf16(Cb[nt], al1, w1.x, w1.y);
        }
        ah0 = nh0; al0 = nl0; ah1 = nh1; al1 = nl1;
    }
#pragma unroll
    for (int nt = 0; nt < 3; nt++)
#pragma unroll
        for (int i = 0; i < 4; i++)
            C[nt][i] = Ca[nt][i] + Cb[nt][i];
}

// ---------------------------------------------------------------------------
// tf32 tensor-core GEMM (phase 1): xg0 = x @ Wih0^T + bih0
// ---------------------------------------------------------------------------
__global__ void __launch_bounds__(256) gemm_tf32_kernel(
    const float* __restrict__ A, const float* __restrict__ W,
    const float* __restrict__ bias, int K, float* __restrict__ C)
{
    __shared__ uint32_t As[128][36];
    __shared__ uint32_t Bs[128][36];

    const int tid  = threadIdx.x;
    const int m0   = blockIdx.y * 128;
    const int n0   = blockIdx.x * 128;
    const int warp = tid >> 5, lane = tid & 31;
    const int wm = warp >> 2, wn = warp & 3;
    const int g  = lane >> 2, tg = lane & 3;

    float acc[4][4][4] = {};

    for (int k0 = 0; k0 < K; k0 += 32) {
#pragma unroll
        for (int r = 0; r < 4; r++) {
            int f   = tid + (r << 8);
            int row = f >> 3;
            int c4  = (f & 7) << 2;
            float4 va = *(const float4*)(A + (size_t)(m0 + row) * K + k0 + c4);
            As[row][c4 + 0] = f2tf(va.x);
            As[row][c4 + 1] = f2tf(va.y);
            As[row][c4 + 2] = f2tf(va.z);
            As[row][c4 + 3] = f2tf(va.w);
            float4 vb = *(const float4*)(W + (size_t)(n0 + row) * K + k0 + c4);
            Bs[row][c4 + 0] = f2tf(vb.x);
            Bs[row][c4 + 1] = f2tf(vb.y);
            Bs[row][c4 + 2] = f2tf(vb.z);
            Bs[row][c4 + 3] = f2tf(vb.w);
        }
        __syncthreads();

#pragma unroll
        for (int s = 0; s < 4; s++) {
            const int kb = s << 3;
            uint32_t a[4][4], b[4][2];
#pragma unroll
            for (int i = 0; i < 4; i++) {
                int r0 = wm * 64 + i * 16 + g;
                a[i][0] = As[r0][kb + tg];
                a[i][1] = As[r0 + 8][kb + tg];
                a[i][2] = As[r0][kb + tg + 4];
                a[i][3] = As[r0 + 8][kb + tg + 4];
            }
#pragma unroll
            for (int jx = 0; jx < 4; jx++) {
                int c = wn * 32 + jx * 8 + g;
                b[jx][0] = Bs[c][kb + tg];
                b[jx][1] = Bs[c][kb + tg + 4];
            }
#pragma unroll
            for (int i = 0; i < 4; i++)
#pragma unroll
                for (int jx = 0; jx < 4; jx++)
                    mma_tf32(acc[i][jx], a[i], b[jx]);
        }
        __syncthreads();
    }

#pragma unroll
    for (int i = 0; i < 4; i++) {
        int r0 = m0 + wm * 64 + i * 16 + g;
#pragma unroll
        for (int jx = 0; jx < 4; jx++) {
            int col = n0 + wn * 32 + jx * 8 + tg * 2;
            float2 bv = *(const float2*)(bias + col);
            float2 o0 = make_float2(acc[i][jx][0] + bv.x, acc[i][jx][1] + bv.y);
            float2 o1 = make_float2(acc[i][jx][2] + bv.x, acc[i][jx][3] + bv.y);
            *(float2*)(C + (size_t)r0 * G3H + col)       = o0;
            *(float2*)(C + (size_t)(r0 + 8) * G3H + col) = o1;
        }
    }
}

// ---------------------------------------------------------------------------
// MERGED two-layer GRU: 257 barrier windows. Window t:
//   warps 0-7  (task 0): h0(t)   = GRU0(h0(t-1), xg0[t])          [t < 256]
//   warps 8-15 (task 1): h1(t-1) = GRU1(h1(t-2), y0(t-1)=h0(t-1)) [t >= 1]
// Task 1 computes the layer-1 input projection INLINE: GEMM over
// [h0(t-1)|h1(t-2)] vs [Wih1|Whh1]. Whh0+Whh1 frags in smem (192KB);
// Wih1 frags from an L2-resident global table with 1-ahead register prefetch.
// All gate math in registers; no intra-window __syncthreads.
// ---------------------------------------------------------------------------
__global__ void __launch_bounds__(512, 1) gru_merged_kernel(
    const float* __restrict__ Whh0, const float* __restrict__ bhh0,
    const float* __restrict__ Whh1, const float* __restrict__ bhh1,
    const float* __restrict__ bih1)
{
    extern __shared__ char smraw[];
    uint4* Wf = (uint4*)smraw;   // slots 0-5: Whh0, slots 6-11: Whh1 (192KB)

    const int tid = threadIdx.x;
    const int bid = blockIdx.x;
    const int jt = bid & 31, mt = bid >> 5;
    const int m0 = mt * 64, j0 = jt * 16;
    const int w = tid >> 5, lane = tid & 31;
    const int task = w >> 3, wsub = w & 7;
    const int wm = wsub >> 1, wn = wsub & 1;
    const int g = lane >> 2, tg = lane & 3;
    const int m16 = mt * 4 + wm;

    unsigned bgen = 0;
    if (tid < 32) bgen = g_slot[mt][jt][0];
    unsigned genc = 0;

    build_wfrag2((uint32_t*)Wf, Whh0, j0, tid, 0, 512);
    build_wfrag2((uint32_t*)Wf, Whh1, j0, tid, 6, 512);

    // Zero h0frag buf0 (h0(-1)) and h1frag buf1 (h1(-1)), group-local slices
    {
        int idx = (bid & 31) * 512 + tid;      // 0..16383
        size_t base = (size_t)mt * 4096;
        uint4 z = make_uint4(0, 0, 0, 0);
        if      (idx < 4096)  g_h0frag[0][0][base + idx] = z;
        else if (idx < 8192)  g_h0frag[0][1][base + idx - 4096] = z;
        else if (idx < 12288) g_h1frag[1][0][base + idx - 8192] = z;
        else                  g_h1frag[1][1][base + idx - 12288] = z;
    }

    const int jc    = j0 + wn * 8 + 2 * tg;   // this thread's first j column
    const int mrow0 = m0 + wm * 16 + g;       // this thread's rows
    const int mrow1 = mrow0 + 8;

    // biases
    float br0[2], bz0[2], bn0[2];             // task 0
    float Br1[2], Bz1[2], bxn1[2], bhn1[2];   // task 1
    if (task == 0) {
        br0[0] = bhh0[jc];          br0[1] = bhh0[jc + 1];
        bz0[0] = bhh0[H_ + jc];     bz0[1] = bhh0[H_ + jc + 1];
        bn0[0] = bhh0[2 * H_ + jc]; bn0[1] = bhh0[2 * H_ + jc + 1];
    } else {
#pragma unroll
        for (int c = 0; c < 2; c++) {
            Br1[c]  = bih1[jc + c] + bhh1[jc + c];
            Bz1[c]  = bih1[H_ + jc + c] + bhh1[H_ + jc + c];
            bxn1[c] = bih1[2 * H_ + jc + c];
            bhn1[c] = bhh1[2 * H_ + jc + c];
        }
    }

    float hreg[4] = {0.f, 0.f, 0.f, 0.f};
    float xr[4], xz[4], xn[4];

    auto prefetch_xg = [&](int tt) {
        size_t b0 = ((size_t)mrow0 * T_ + tt) * G3H + jc;
        size_t b1 = ((size_t)mrow1 * T_ + tt) * G3H + jc;
        float2 v;
        v = *(const float2*)(g_xg + b0);           xr[0] = v.x; xr[1] = v.y;
        v = *(const float2*)(g_xg + b0 + H_);      xz[0] = v.x; xz[1] = v.y;
        v = *(const float2*)(g_xg + b0 + 2 * H_);  xn[0] = v.x; xn[1] = v.y;
        v = *(const float2*)(g_xg + b1);           xr[2] = v.x; xr[3] = v.y;
        v = *(const float2*)(g_xg + b1 + H_);      xz[2] = v.x; xz[3] = v.y;
        v = *(const float2*)(g_xg + b1 + 2 * H_);  xn[2] = v.x; xn[3] = v.y;
    };
    if (task == 0) prefetch_xg(0);

    slot_barrier(mt, jt, bgen + (++genc));

    const size_t fb0 = (size_t)(m16 * 32) * 32 + lane;
    const size_t sb  = ((size_t)(m16 * 32) + jt) * 32 + lane;
    const uint4* __restrict__ Wg = g_wfrag1 + (size_t)jt * 6144;  // Wih1 table

    for (int t = 0; t <= T_; t++) {
        if (task == 0) {
            if (t < T_) {
                const uint4* __restrict__ Ahi = g_h0frag[t & 1][0];
                const uint4* __restrict__ Alo = g_h0frag[t & 1][1];
                float C[3][4];
                gemm48(C, Wf, wn * 3, 0, Ahi, Alo, fb0, lane, 16);

                float hv[4];
#pragma unroll
                for (int i = 0; i < 4; i++) {
                    float r  = sigf(xr[i] + C[0][i] + br0[i & 1]);
                    float z  = sigf(xz[i] + C[1][i] + bz0[i & 1]);
                    float nv = tanhf(xn[i] + r * (C[2][i] + bn0[i & 1]));
                    float h  = (1.0f - z) * nv + z * hreg[i];
                    hreg[i] = h; hv[i] = h;
                }
                float fh[4], fl[4];
#pragma unroll
                for (int q = 0; q < 4; q++) {
                    fh[q] = __bfloat162float(__float2bfloat16(hv[q]));
                    fl[q] = hv[q] - fh[q];
                }
                uint2 hiu = make_uint2(pack2_bf16(fh[0], fh[1]), pack2_bf16(fh[2], fh[3]));
                uint2 lou = make_uint2(pack2_bf16(fl[0], fl[1]), pack2_bf16(fl[2], fl[3]));
                const int nb = (t + 1) & 1;
                ((uint2*)&g_h0frag[nb][0][sb])[wn] = hiu;
                ((uint2*)&g_h0frag[nb][1][sb])[wn] = lou;

                if (t < T_ - 1) prefetch_xg(t + 1);
            }
        } else if (t >= 1) {
            const uint4* __restrict__ A0h = g_h0frag[t & 1][0];
            const uint4* __restrict__ A0l = g_h0frag[t & 1][1];
            const uint4* __restrict__ A1h = g_h1frag[t & 1][0];
            const uint4* __restrict__ A1l = g_h1frag[t & 1][1];

            // 6 independent accumulator chains: {r,z,n} x {ih, hh}
            float Cri[4] = {}, Crh[4] = {}, Czi[4] = {}, Czh[4] = {};
            float Cni[4] = {}, Cnh[4] = {};

            uint4 a0h = A0h[fb0], a0l = A0l[fb0];
            uint4 a1h = A1h[fb0], a1l = A1l[fb0];
            uint4 wi0 = Wg[((wn * 3 + 0) * 32) * 32 + lane];
            uint4 wi1 = Wg[((wn * 3 + 1) * 32) * 32 + lane];
            uint4 wi2 = Wg[((wn * 3 + 2) * 32) * 32 + lane];

#pragma unroll 4
            for (int ks = 0; ks < 32; ks++) {
                uint4 n0h, n0l, n1h, n1l, nw0, nw1, nw2;
                if (ks < 31) {
                    size_t nf = fb0 + (ks + 1) * 32;
                    n0h = A0h[nf]; n0l = A0l[nf];
                    n1h = A1h[nf]; n1l = A1l[nf];
                    nw0 = Wg[((wn * 3 + 0) * 32 + ks + 1) * 32 + lane];
                    nw1 = Wg[((wn * 3 + 1) * 32 + ks + 1) * 32 + lane];
                    nw2 = Wg[((wn * 3 + 2) * 32 + ks + 1) * 32 + lane];
                }
                // hh-side (Whh1, smem slots 6..11) against h1(t-2)
                uint4 wh0 = Wf[((6 + wn * 3 + 0) * 32 + ks) * 32 + lane];
                mma_bf16(Crh, a1h, wh0.x, wh0.y);
                mma_bf16(Crh, a1h, wh0.z, wh0.w);
                mma_bf16(Crh, a1l, wh0.x, wh0.y);
                uint4 wh1 = Wf[((6 + wn * 3 + 1) * 32 + ks) * 32 + lane];
                mma_bf16(Czh, a1h, wh1.x, wh1.y);
                mma_bf16(Czh, a1h, wh1.z, wh1.w);
                mma_bf16(Czh, a1l, wh1.x, wh1.y);
                uint4 wh2 = Wf[((6 + wn * 3 + 2) * 32 + ks) * 32 + lane];
                mma_bf16(Cnh, a1h, wh2.x, wh2.y);
                mma_bf16(Cnh, a1h, wh2.z, wh2.w);
                mma_bf16(Cnh, a1l, wh2.x, wh2.y);
                // ih-side (Wih1, global table) against h0(t-1)
                mma_bf16(Cri, a0h, wi0.x, wi0.y);
                mma_bf16(Cri, a0h, wi0.z, wi0.w);
                mma_bf16(Cri, a0l, wi0.x, wi0.y);
                mma_bf16(Czi, a0h, wi1.x, wi1.y);
                mma_bf16(Czi, a0h, wi1.z, wi1.w);
                mma_bf16(Czi, a0l, wi1.x, wi1.y);
                mma_bf16(Cni, a0h, wi2.x, wi2.y);
                mma_bf16(Cni, a0h, wi2.z, wi2.w);
                mma_bf16(Cni, a0l, wi2.x, wi2.y);

                a0h = n0h; a0l = n0l; a1h = n1h; a1l = n1l;
                wi0 = nw0; wi1 = nw1; wi2 = nw2;
            }

            float hv[4];
#pragma unroll
            for (int i = 0; i < 4; i++) {
                float r  = sigf(Cri[i] + Crh[i] + Br1[i & 1]);
                float z  = sigf(Czi[i] + Czh[i] + Bz1[i & 1]);
                float nv = tanhf(Cni[i] + bxn1[i & 1] + r * (Cnh[i] + bhn1[i & 1]));
                float h  = (1.0f - z) * nv + z * hreg[i];
                hreg[i] = h; hv[i] = h;
            }
            if (t == T_) {
                *(float2*)(g_hT + (size_t)mrow0 * H_ + jc) = make_float2(hv[0], hv[1]);
                *(float2*)(g_hT + (size_t)mrow1 * H_ + jc) = make_float2(hv[2], hv[3]);
            } else {
                float fh[4], fl[4];
#pragma unroll
                for (int q = 0; q < 4; q++) {
                    fh[q] = __bfloat162float(__float2bfloat16(hv[q]));
                    fl[q] = hv[q] - fh[q];
                }
                uint2 hiu = make_uint2(pack2_bf16(fh[0], fh[1]), pack2_bf16(fh[2], fh[3]));
                uint2 lou = make_uint2(pack2_bf16(fl[0], fl[1]), pack2_bf16(fl[2], fl[3]));
                const int nb = (t + 1) & 1;
                ((uint2*)&g_h1frag[nb][0][sb])[wn] = hiu;
                ((uint2*)&g_h1frag[nb][1][sb])[wn] = lou;
            }
        }

        slot_barrier(mt, jt, bgen + (++genc));
    }
}

// ---------------------------------------------------------------------------
// Head: out = relu(relu(hT) @ fc1^T + b1) @ fc2^T + b2
// ---------------------------------------------------------------------------
__global__ void __launch_bounds__(512) head_kernel(
    const float* __restrict__ w1, const float* __restrict__ b1,
    const float* __restrict__ w2, const float* __restrict__ b2,
    float* __restrict__ out)
{
    __shared__ float sh[H_];
    __shared__ float s1[128];
    const int b = blockIdx.x;
    const int tid = threadIdx.x;
    const int w = tid >> 5, lane = tid & 31;

    sh[tid] = fmaxf(g_hT[(size_t)b * H_ + tid], 0.0f);
    __syncthreads();

#pragma unroll
    for (int oo = 0; oo < 8; oo++) {
        int o = w * 8 + oo;
        const float* wr = w1 + (size_t)o * H_;
        float acc = 0.f;
#pragma unroll
        for (int c = 0; c < 4; c++) {
            int k = c * 128 + lane * 4;
            float4 wv = *(const float4*)(wr + k);
            float4 hv = *(const float4*)(&sh[k]);
            acc += wv.x * hv.x + wv.y * hv.y + wv.z * hv.z + wv.w * hv.w;
        }
#pragma unroll
        for (int off = 16; off; off >>= 1)
            acc += __shfl_down_sync(0xFFFFFFFFu, acc, off);
        if (lane == 0) s1[o] = fmaxf(acc + b1[o], 0.0f);
    }
    __syncthreads();

    if (w < 10) {
        const float* wr = w2 + (size_t)w * 128;
        float acc = 0.f;
#pragma unroll
        for (int c = 0; c < 4; c++) {
            int k = lane + c * 32;
            acc += s1[k] * wr[k];
        }
#pragma unroll
        for (int off = 16; off; off >>= 1)
            acc += __shfl_down_sync(0xFFFFFFFFu, acc, off);
        if (lane == 0) out[(size_t)b * 10 + w] = acc + b2[w];
    }
}

// ---------------------------------------------------------------------------
// Launch
// ---------------------------------------------------------------------------
extern "C" void kernel_launch(void* const* d_in, const int* in_sizes, int n_in,
                              void* d_out, int out_size)
{
    const float* x    = (const float*)d_in[0];
    const float* Wih0 = (const float*)d_in[1];
    const float* Whh0 = (const float*)d_in[2];
    const float* bih0 = (const float*)d_in[3];
    const float* bhh0 = (const float*)d_in[4];
    const float* Wih1 = (const float*)d_in[5];
    const float* Whh1 = (const float*)d_in[6];
    const float* bih1 = (const float*)d_in[7];
    const float* bhh1 = (const float*)d_in[8];
    const float* fc1w = (const float*)d_in[9];
    const float* fc1b = (const float*)d_in[10];
    const float* fc2w = (const float*)d_in[11];
    const float* fc2b = (const float*)d_in[12];
    float* out = (float*)d_out;

    float* xg_ptr = nullptr;
    cudaGetSymbolAddress((void**)&xg_ptr, g_xg);

    const int merged_smem = 12 * 32 * 32 * 16;   // 192KB
    cudaFuncSetAttribute((const void*)gru_merged_kernel,
                         cudaFuncAttributeMaxDynamicSharedMemorySize, merged_smem);

    dim3 gemm_grid(G3H / 128, BT / 128);  // (12, 512)

    // Phase 0: Wih1 fragment table (3MB, L2-resident)
    build_wih1_kernel<<<32, 512>>>(Wih1);

    // Phase 1: xg0 = x @ W_ih0^T + b_ih0   (K = 128)
    gemm_tf32_kernel<<<gemm_grid, 256>>>(x, Wih0, bih0, D_, xg_ptr);

    // Phase 2: merged two-layer GRU (257 barrier windows)
    gru_merged_kernel<<<128, 512, merged_smem>>>(Whh0, bhh0, Whh1, bhh1, bih1);

    // Phase 3: MLP head
    head_kernel<<<B_, 512>>>(fc1w, fc1b, fc2w, fc2b, out);
}